// round 1
// baseline (speedup 1.0000x reference)
#include <cuda_runtime.h>
#include <math.h>

#define B_ 2
#define S_ 2048
#define E_ 1024
#define H_ 16
#define DH 64

// Scratch (device globals — no allocation allowed)
__device__ float g_Q[(size_t)B_ * H_ * S_ * DH];   // [B,H,S,Dh]
__device__ float g_V[(size_t)B_ * H_ * S_ * DH];   // [B,H,S,Dh]
__device__ int   g_bkt[B_ * H_ * S_];              // [B,H,S]

// ---------------------------------------------------------------------------
// Projection GEMM: C[m,n] = sum_k x[m,k] * W[n,k] + bias[n]
// M=4096 (b*S+s), N=1024 (h*64+d), K=1024.  Output scattered to [B,H,S,Dh].
// grid: (16, 64, 2)  z=0 -> Q, z=1 -> V.  64x64 tile, BK=16, 4x4 per thread.
// ---------------------------------------------------------------------------
__global__ __launch_bounds__(256, 2)
void proj_kernel(const float* __restrict__ x,
                 const float* __restrict__ Wq, const float* __restrict__ bq,
                 const float* __restrict__ Wv, const float* __restrict__ bv)
{
    const float* W    = blockIdx.z ? Wv : Wq;
    const float* bias = blockIdx.z ? bv : bq;
    float* Out        = blockIdx.z ? g_V : g_Q;

    __shared__ float As[64][17];
    __shared__ float Bs[64][17];

    const int tid = threadIdx.x;
    const int tx = tid & 15, ty = tid >> 4;
    const int m0 = blockIdx.y << 6;
    const int n0 = blockIdx.x << 6;
    const int lr = tid >> 2;           // 0..63
    const int lc = (tid & 3) << 2;     // 0,4,8,12

    float acc[4][4];
#pragma unroll
    for (int i = 0; i < 4; i++)
#pragma unroll
        for (int j = 0; j < 4; j++) acc[i][j] = 0.f;

    const float* xg = x + (size_t)(m0 + lr) * E_ + lc;
    const float* wg = W + (size_t)(n0 + lr) * E_ + lc;

    for (int k0 = 0; k0 < E_; k0 += 16) {
        float4 a4 = *(const float4*)(xg + k0);
        float4 b4 = *(const float4*)(wg + k0);
        As[lr][lc + 0] = a4.x; As[lr][lc + 1] = a4.y;
        As[lr][lc + 2] = a4.z; As[lr][lc + 3] = a4.w;
        Bs[lr][lc + 0] = b4.x; Bs[lr][lc + 1] = b4.y;
        Bs[lr][lc + 2] = b4.z; Bs[lr][lc + 3] = b4.w;
        __syncthreads();
#pragma unroll
        for (int k = 0; k < 16; k++) {
            float a[4], bb[4];
#pragma unroll
            for (int i = 0; i < 4; i++) a[i]  = As[ty * 4 + i][k];
#pragma unroll
            for (int j = 0; j < 4; j++) bb[j] = Bs[tx * 4 + j][k];
#pragma unroll
            for (int i = 0; i < 4; i++)
#pragma unroll
                for (int j = 0; j < 4; j++)
                    acc[i][j] = fmaf(a[i], bb[j], acc[i][j]);
        }
        __syncthreads();
    }

    const int h = blockIdx.x;  // n0/64
#pragma unroll
    for (int i = 0; i < 4; i++) {
        int m = m0 + ty * 4 + i;
        int b = m >> 11, s = m & (S_ - 1);
        float* orow = Out + (((size_t)(b * H_ + h)) * S_ + s) * DH;
#pragma unroll
        for (int j = 0; j < 4; j++) {
            int d = tx * 4 + j;
            orow[d] = acc[i][j] + bias[n0 + d];
        }
    }
}

// ---------------------------------------------------------------------------
// LSH buckets: proj_n = sum_d q_d * hp[d,n] + hp[64,n];  bit n = (proj>=0)
// One thread per (b,h,s) row.
// ---------------------------------------------------------------------------
__global__ __launch_bounds__(256)
void bucket_kernel(const float* __restrict__ hp)
{
    __shared__ float shp[65 * 6];
    for (int i = threadIdx.x; i < 65 * 6; i += 256) shp[i] = hp[i];
    __syncthreads();

    int idx = blockIdx.x * 256 + threadIdx.x;      // bh*S + s
    const float* q = g_Q + (size_t)idx * DH;
    float proj[6];
#pragma unroll
    for (int n = 0; n < 6; n++) proj[n] = shp[64 * 6 + n];  // ones column
    for (int d = 0; d < DH; d++) {
        float qd = q[d];
#pragma unroll
        for (int n = 0; n < 6; n++) proj[n] = fmaf(qd, shp[d * 6 + n], proj[n]);
    }
    int bucket = 0;
#pragma unroll
    for (int n = 0; n < 6; n++) if (proj[n] >= 0.f) bucket |= (1 << n);
    g_bkt[idx] = bucket;
}

// ---------------------------------------------------------------------------
// Flash attention with LSH coeff:
//   logit = (q.k / 32) * (62 + [bucket_s == bucket_t])
// 64-row tiles per block, 64-col K/V tiles, online softmax.
// grid: (S/64, B*H), 256 threads (16x16, 4x4 score micro-tile).
// ---------------------------------------------------------------------------
__global__ __launch_bounds__(256, 2)
void attn_kernel(float* __restrict__ out)
{
    extern __shared__ float sm[];
    float* Vs = sm;                     // [64][64] (16B-aligned, float4 reads)
    float* Qs = Vs + 64 * 64;           // [64][65]
    float* Ks = Qs + 64 * 65;           // [64][65]
    float* Ps = Ks + 64 * 65;           // [64][65]
    int*  bqs = (int*)(Ps + 64 * 65);   // [64]
    int*  bks = bqs + 64;               // [64]

    const int bh = blockIdx.y;
    const int b = bh >> 4, h = bh & 15;
    const int s0 = blockIdx.x << 6;
    const float* Qg = g_Q + (size_t)bh * S_ * DH;
    const float* Vg = g_V + (size_t)bh * S_ * DH;
    const int*  bkp = g_bkt + bh * S_;

    const int tid = threadIdx.x;
    const int tx = tid & 15, ty = tid >> 4;

    // load Q tile
#pragma unroll
    for (int u = 0; u < 4; u++) {
        int lin = u * 1024 + tid * 4;
        int r = lin >> 6, c = lin & 63;
        float4 v = *(const float4*)(Qg + (size_t)(s0 + r) * DH + c);
        Qs[r * 65 + c]     = v.x; Qs[r * 65 + c + 1] = v.y;
        Qs[r * 65 + c + 2] = v.z; Qs[r * 65 + c + 3] = v.w;
    }
    if (tid < 64) bqs[tid] = bkp[s0 + tid];

    float m_i[4], l_i[4], o[4][4];
#pragma unroll
    for (int i = 0; i < 4; i++) {
        m_i[i] = -INFINITY; l_i[i] = 0.f;
#pragma unroll
        for (int j = 0; j < 4; j++) o[i][j] = 0.f;
    }
    __syncthreads();

    for (int t0 = 0; t0 < S_; t0 += 64) {
        // load K (=Q rows) and V tiles
#pragma unroll
        for (int u = 0; u < 4; u++) {
            int lin = u * 1024 + tid * 4;
            int r = lin >> 6, c = lin & 63;
            float4 kv = *(const float4*)(Qg + (size_t)(t0 + r) * DH + c);
            Ks[r * 65 + c]     = kv.x; Ks[r * 65 + c + 1] = kv.y;
            Ks[r * 65 + c + 2] = kv.z; Ks[r * 65 + c + 3] = kv.w;
            float4 vv = *(const float4*)(Vg + (size_t)(t0 + r) * DH + c);
            *(float4*)(Vs + r * 64 + c) = vv;
        }
        if (tid < 64) bks[tid] = bkp[t0 + tid];
        __syncthreads();

        // S = Q . K^T
        float sc[4][4];
#pragma unroll
        for (int i = 0; i < 4; i++)
#pragma unroll
            for (int j = 0; j < 4; j++) sc[i][j] = 0.f;

#pragma unroll 8
        for (int k = 0; k < 64; k++) {
            float a[4], bb[4];
#pragma unroll
            for (int i = 0; i < 4; i++) a[i]  = Qs[(ty * 4 + i) * 65 + k];
#pragma unroll
            for (int j = 0; j < 4; j++) bb[j] = Ks[(tx * 4 + j) * 65 + k];
#pragma unroll
            for (int i = 0; i < 4; i++)
#pragma unroll
                for (int j = 0; j < 4; j++)
                    sc[i][j] = fmaf(a[i], bb[j], sc[i][j]);
        }

        // coeff + online softmax. 63/32 and 62/32 are exact in binary fp.
#pragma unroll
        for (int i = 0; i < 4; i++) {
            int bqv = bqs[ty * 4 + i];
            float rm = -INFINITY;
#pragma unroll
            for (int j = 0; j < 4; j++) {
                float cf = (bqv == bks[tx * 4 + j]) ? 1.96875f : 1.9375f;
                sc[i][j] *= cf;
                rm = fmaxf(rm, sc[i][j]);
            }
#pragma unroll
            for (int off = 8; off > 0; off >>= 1)
                rm = fmaxf(rm, __shfl_xor_sync(0xffffffffu, rm, off));
            float mn = fmaxf(m_i[i], rm);
            float corr = __expf(m_i[i] - mn);   // first iter: exp(-inf)=0
            float ps = 0.f;
#pragma unroll
            for (int j = 0; j < 4; j++) {
                float p = __expf(sc[i][j] - mn);
                Ps[(ty * 4 + i) * 65 + tx * 4 + j] = p;
                ps += p;
            }
#pragma unroll
            for (int off = 8; off > 0; off >>= 1)
                ps += __shfl_xor_sync(0xffffffffu, ps, off);
            l_i[i] = l_i[i] * corr + ps;
            m_i[i] = mn;
#pragma unroll
            for (int j = 0; j < 4; j++) o[i][j] *= corr;
        }
        __syncthreads();

        // O += P @ V
#pragma unroll 8
        for (int k = 0; k < 64; k++) {
            float p[4];
#pragma unroll
            for (int i = 0; i < 4; i++) p[i] = Ps[(ty * 4 + i) * 65 + k];
            float4 v4 = *(const float4*)(Vs + k * 64 + tx * 4);
            float vv[4] = {v4.x, v4.y, v4.z, v4.w};
#pragma unroll
            for (int i = 0; i < 4; i++)
#pragma unroll
                for (int j = 0; j < 4; j++)
                    o[i][j] = fmaf(p[i], vv[j], o[i][j]);
        }
        __syncthreads();
    }

    // normalize + write out[b, s, h, d]
#pragma unroll
    for (int i = 0; i < 4; i++) {
        int s = s0 + ty * 4 + i;
        float inv = 1.f / l_i[i];
        float* orow = out + (((size_t)(b * S_ + s)) * H_ + h) * DH;
#pragma unroll
        for (int j = 0; j < 4; j++)
            orow[tx * 4 + j] = o[i][j] * inv;
    }
}

// ---------------------------------------------------------------------------
extern "C" void kernel_launch(void* const* d_in, const int* in_sizes, int n_in,
                              void* d_out, int out_size)
{
    const float* x  = (const float*)d_in[0];
    const float* Wq = (const float*)d_in[1];
    const float* bq = (const float*)d_in[2];
    const float* Wv = (const float*)d_in[3];
    const float* bv = (const float*)d_in[4];
    const float* hp = (const float*)d_in[5];
    float* out = (float*)d_out;

    dim3 gProj(H_, (B_ * S_) / 64, 2);
    proj_kernel<<<gProj, 256>>>(x, Wq, bq, Wv, bv);

    bucket_kernel<<<(B_ * H_ * S_) / 256, 256>>>(hp);

    const size_t attnSmem = (size_t)(64 * 64 + 3 * 64 * 65) * sizeof(float)
                          + 128 * sizeof(int);
    cudaFuncSetAttribute(attn_kernel,
                         cudaFuncAttributeMaxDynamicSharedMemorySize,
                         (int)attnSmem);
    attn_kernel<<<dim3(S_ / 64, B_ * H_), 256, attnSmem>>>(out);
}

// round 2
// speedup vs baseline: 1.6538x; 1.6538x over previous
#include <cuda_runtime.h>
#include <math.h>

#define B_ 2
#define S_ 2048
#define E_ 1024
#define H_ 16
#define DH 64

// Scratch (device globals — no allocation allowed)
__device__ float g_Q[(size_t)B_ * H_ * S_ * DH];   // [B,H,S,Dh]
__device__ float g_V[(size_t)B_ * H_ * S_ * DH];   // [B,H,S,Dh]
__device__ int   g_bkt[B_ * H_ * S_];              // [B,H,S]

typedef unsigned long long u64;
union F2 { u64 u; float2 f; };

__device__ __forceinline__ u64 dup2(float x) {
    u64 r; asm("mov.b64 %0,{%1,%1};" : "=l"(r) : "f"(x)); return r;
}
__device__ __forceinline__ void fma2(u64& d, u64 a, u64 b) {
    asm("fma.rn.f32x2 %0,%1,%2,%3;" : "=l"(d) : "l"(a), "l"(b), "l"(d));
}
__device__ __forceinline__ u64 mul2(u64 a, u64 b) {
    u64 r; asm("mul.rn.f32x2 %0,%1,%2;" : "=l"(r) : "l"(a), "l"(b)); return r;
}

// ---------------------------------------------------------------------------
// Projection GEMM: C[m,n] = sum_k x[m,k] * W[n,k] + bias[n]
// 128x128 tile, BK=16, 256 threads, 8x8 microtile, packed f32x2 FMA
// (accumulator pairs along m). Smem tiles stored k-major (transposed).
// grid: (8, 32, 2)  z=0 -> Q, z=1 -> V.
// ---------------------------------------------------------------------------
__global__ __launch_bounds__(256, 2)
void proj_kernel(const float* __restrict__ x,
                 const float* __restrict__ Wq, const float* __restrict__ bq,
                 const float* __restrict__ Wv, const float* __restrict__ bv)
{
    const float* W    = blockIdx.z ? Wv : Wq;
    const float* bias = blockIdx.z ? bv : bq;
    float* Out        = blockIdx.z ? g_V : g_Q;

    __shared__ float At[16][132];   // [k][m]
    __shared__ float Bt[16][132];   // [k][n]

    const int tid = threadIdx.x;
    const int tn = tid & 15, tm = tid >> 4;
    const int m0 = blockIdx.y << 7;
    const int n0 = blockIdx.x << 7;

    u64 acc[4][8];
#pragma unroll
    for (int p = 0; p < 4; p++)
#pragma unroll
        for (int j = 0; j < 8; j++) acc[p][j] = 0ull;

    for (int k0 = 0; k0 < E_; k0 += 16) {
        // load + transpose both tiles: 128 rows x 16 k
#pragma unroll
        for (int it = 0; it < 2; it++) {
            int idx = it * 256 + tid;
            int row = idx >> 2;
            int c = (idx & 3) << 2;
            float4 av = *(const float4*)(x + (size_t)(m0 + row) * E_ + k0 + c);
            At[c + 0][row] = av.x; At[c + 1][row] = av.y;
            At[c + 2][row] = av.z; At[c + 3][row] = av.w;
            float4 bw = *(const float4*)(W + (size_t)(n0 + row) * E_ + k0 + c);
            Bt[c + 0][row] = bw.x; Bt[c + 1][row] = bw.y;
            Bt[c + 2][row] = bw.z; Bt[c + 3][row] = bw.w;
        }
        __syncthreads();

#pragma unroll
        for (int k = 0; k < 16; k++) {
            ulonglong2 a01 = *(const ulonglong2*)&At[k][tm * 8];
            ulonglong2 a23 = *(const ulonglong2*)&At[k][tm * 8 + 4];
            float4 b0 = *(const float4*)&Bt[k][tn * 8];
            float4 b1 = *(const float4*)&Bt[k][tn * 8 + 4];
            u64 bd[8];
            bd[0] = dup2(b0.x); bd[1] = dup2(b0.y);
            bd[2] = dup2(b0.z); bd[3] = dup2(b0.w);
            bd[4] = dup2(b1.x); bd[5] = dup2(b1.y);
            bd[6] = dup2(b1.z); bd[7] = dup2(b1.w);
            u64 ap[4] = {a01.x, a01.y, a23.x, a23.y};
#pragma unroll
            for (int p = 0; p < 4; p++)
#pragma unroll
                for (int j = 0; j < 8; j++)
                    fma2(acc[p][j], ap[p], bd[j]);
        }
        __syncthreads();
    }

    // epilogue: scatter to [B,H,S,Dh] with bias
    const int nb = n0 + tn * 8;
    const int h = nb >> 6;
    const int d = nb & 63;
    float bi[8];
#pragma unroll
    for (int j = 0; j < 8; j++) bi[j] = bias[nb + j];

#pragma unroll
    for (int p = 0; p < 4; p++) {
#pragma unroll
        for (int sub = 0; sub < 2; sub++) {
            int m = m0 + tm * 8 + 2 * p + sub;
            int b = m >> 11, s = m & (S_ - 1);
            float* orow = Out + (((size_t)(b * H_ + h)) * S_ + s) * DH + d;
            float v[8];
#pragma unroll
            for (int j = 0; j < 8; j++) {
                F2 u; u.u = acc[p][j];
                v[j] = (sub ? u.f.y : u.f.x) + bi[j];
            }
            *(float4*)(orow)     = make_float4(v[0], v[1], v[2], v[3]);
            *(float4*)(orow + 4) = make_float4(v[4], v[5], v[6], v[7]);
        }
    }
}

// ---------------------------------------------------------------------------
// LSH buckets (unchanged): one thread per (b,h,s) row.
// ---------------------------------------------------------------------------
__global__ __launch_bounds__(256)
void bucket_kernel(const float* __restrict__ hp)
{
    __shared__ float shp[65 * 6];
    for (int i = threadIdx.x; i < 65 * 6; i += 256) shp[i] = hp[i];
    __syncthreads();

    int idx = blockIdx.x * 256 + threadIdx.x;
    const float* q = g_Q + (size_t)idx * DH;
    float proj[6];
#pragma unroll
    for (int n = 0; n < 6; n++) proj[n] = shp[64 * 6 + n];
    for (int d = 0; d < DH; d++) {
        float qd = q[d];
#pragma unroll
        for (int n = 0; n < 6; n++) proj[n] = fmaf(qd, shp[d * 6 + n], proj[n]);
    }
    int bucket = 0;
#pragma unroll
    for (int n = 0; n < 6; n++) if (proj[n] >= 0.f) bucket |= (1 << n);
    g_bkt[idx] = bucket;
}

// ---------------------------------------------------------------------------
// Flash attention with LSH coeff, packed f32x2 math.
//   logit = (q.k / 32) * (62 + [bucket_s == bucket_t])
// 64x64 tiles, 256 threads (16x16, 4x4 microtile, score pairs along t).
// Qt/Kt stored d-major (transposed, stride 68, conflict-free stores);
// Vs/Ps row-major stride 68.
// ---------------------------------------------------------------------------
__global__ __launch_bounds__(256, 2)
void attn_kernel(float* __restrict__ out)
{
    extern __shared__ float sm[];
    float* Qt = sm;                       // [64 d][68]
    float* Kt = Qt + 64 * 68;             // [64 d][68]
    float* Vs = Kt + 64 * 68;             // [64 t][68]
    float* Ps = Vs + 64 * 68;             // [64 s][68]
    int*  bqs = (int*)(Ps + 64 * 68);     // [64]
    int*  bks = bqs + 64;                 // [64]

    const int bh = blockIdx.y;
    const int b = bh >> 4, h = bh & 15;
    const int s0 = blockIdx.x << 6;
    const float* Qg = g_Q + (size_t)bh * S_ * DH;
    const float* Vg = g_V + (size_t)bh * S_ * DH;
    const int*  bkp = g_bkt + bh * S_;

    const int tid = threadIdx.x;
    const int tx = tid & 15, ty = tid >> 4;
    const int tx4 = tx << 2, ty4 = ty << 2;

    // transposed-load mapping: conflict-free STS with stride 68
    const int lr = tid & 15;          // row within 16-row slab
    const int lc = (tid >> 4) << 2;   // column group (d)

    // load Q tile (transposed)
#pragma unroll
    for (int u = 0; u < 4; u++) {
        int r = u * 16 + lr;
        float4 v = *(const float4*)(Qg + (size_t)(s0 + r) * DH + lc);
        Qt[(lc + 0) * 68 + r] = v.x; Qt[(lc + 1) * 68 + r] = v.y;
        Qt[(lc + 2) * 68 + r] = v.z; Qt[(lc + 3) * 68 + r] = v.w;
    }
    if (tid < 64) bqs[tid] = bkp[s0 + tid];

    float m_i[4], l_i[4];
    u64 o2[4][2];
#pragma unroll
    for (int i = 0; i < 4; i++) {
        m_i[i] = -INFINITY; l_i[i] = 0.f;
        o2[i][0] = 0ull; o2[i][1] = 0ull;
    }
    __syncthreads();

    for (int t0 = 0; t0 < S_; t0 += 64) {
        // load K tile (transposed) + V tile (row-major)
#pragma unroll
        for (int u = 0; u < 4; u++) {
            int r = u * 16 + lr;
            float4 kv = *(const float4*)(Qg + (size_t)(t0 + r) * DH + lc);
            Kt[(lc + 0) * 68 + r] = kv.x; Kt[(lc + 1) * 68 + r] = kv.y;
            Kt[(lc + 2) * 68 + r] = kv.z; Kt[(lc + 3) * 68 + r] = kv.w;
            float4 vv = *(const float4*)(Vg + (size_t)(t0 + r) * DH + lc);
            *(float4*)(Vs + r * 68 + lc) = vv;
        }
        if (tid < 64) bks[tid] = bkp[t0 + tid];
        __syncthreads();

        // S = Q . K^T   (pairs along t)
        u64 sc2[4][2];
#pragma unroll
        for (int i = 0; i < 4; i++) { sc2[i][0] = 0ull; sc2[i][1] = 0ull; }

#pragma unroll 8
        for (int k = 0; k < 64; k++) {
            float4 aq = *(const float4*)&Qt[k * 68 + ty4];
            ulonglong2 bk = *(const ulonglong2*)&Kt[k * 68 + tx4];
            u64 a0 = dup2(aq.x), a1 = dup2(aq.y), a2 = dup2(aq.z), a3 = dup2(aq.w);
            fma2(sc2[0][0], a0, bk.x); fma2(sc2[0][1], a0, bk.y);
            fma2(sc2[1][0], a1, bk.x); fma2(sc2[1][1], a1, bk.y);
            fma2(sc2[2][0], a2, bk.x); fma2(sc2[2][1], a2, bk.y);
            fma2(sc2[3][0], a3, bk.x); fma2(sc2[3][1], a3, bk.y);
        }

        // coeff + online softmax (63/32, 62/32 exact in fp)
#pragma unroll
        for (int i = 0; i < 4; i++) {
            float s[4];
            { F2 u0; u0.u = sc2[i][0]; s[0] = u0.f.x; s[1] = u0.f.y; }
            { F2 u1; u1.u = sc2[i][1]; s[2] = u1.f.x; s[3] = u1.f.y; }
            int bqv = bqs[ty4 + i];
            float rm = -INFINITY;
#pragma unroll
            for (int j = 0; j < 4; j++) {
                float cf = (bqv == bks[tx4 + j]) ? 1.96875f : 1.9375f;
                s[j] *= cf;
                rm = fmaxf(rm, s[j]);
            }
#pragma unroll
            for (int off = 8; off > 0; off >>= 1)
                rm = fmaxf(rm, __shfl_xor_sync(0xffffffffu, rm, off));
            float mn = fmaxf(m_i[i], rm);
            float corr = __expf(m_i[i] - mn);
            float p0 = __expf(s[0] - mn);
            float p1 = __expf(s[1] - mn);
            float p2 = __expf(s[2] - mn);
            float p3 = __expf(s[3] - mn);
            *(float4*)&Ps[(ty4 + i) * 68 + tx4] = make_float4(p0, p1, p2, p3);
            float ps = (p0 + p1) + (p2 + p3);
#pragma unroll
            for (int off = 8; off > 0; off >>= 1)
                ps += __shfl_xor_sync(0xffffffffu, ps, off);
            l_i[i] = l_i[i] * corr + ps;
            m_i[i] = mn;
            u64 c2 = dup2(corr);
            o2[i][0] = mul2(o2[i][0], c2);
            o2[i][1] = mul2(o2[i][1], c2);
        }
        __syncwarp();   // P producers for my rows are in my warp

        // O += P @ V   (pairs along d)
#pragma unroll 8
        for (int k = 0; k < 64; k++) {
            ulonglong2 v2 = *(const ulonglong2*)&Vs[k * 68 + tx4];
            float p0 = Ps[(ty4 + 0) * 68 + k];
            float p1 = Ps[(ty4 + 1) * 68 + k];
            float p2 = Ps[(ty4 + 2) * 68 + k];
            float p3 = Ps[(ty4 + 3) * 68 + k];
            u64 d0 = dup2(p0), d1 = dup2(p1), d2 = dup2(p2), d3 = dup2(p3);
            fma2(o2[0][0], d0, v2.x); fma2(o2[0][1], d0, v2.y);
            fma2(o2[1][0], d1, v2.x); fma2(o2[1][1], d1, v2.y);
            fma2(o2[2][0], d2, v2.x); fma2(o2[2][1], d2, v2.y);
            fma2(o2[3][0], d3, v2.x); fma2(o2[3][1], d3, v2.y);
        }
        __syncthreads();
    }

    // normalize + write out[b, s, h, d]
#pragma unroll
    for (int i = 0; i < 4; i++) {
        int s = s0 + ty4 + i;
        float inv = 1.f / l_i[i];
        float* orow = out + (((size_t)(b * S_ + s)) * H_ + h) * DH;
        F2 u0, u1; u0.u = o2[i][0]; u1.u = o2[i][1];
        *(float4*)(orow + tx4) = make_float4(u0.f.x * inv, u0.f.y * inv,
                                             u1.f.x * inv, u1.f.y * inv);
    }
}

// ---------------------------------------------------------------------------
extern "C" void kernel_launch(void* const* d_in, const int* in_sizes, int n_in,
                              void* d_out, int out_size)
{
    const float* x  = (const float*)d_in[0];
    const float* Wq = (const float*)d_in[1];
    const float* bq = (const float*)d_in[2];
    const float* Wv = (const float*)d_in[3];
    const float* bv = (const float*)d_in[4];
    const float* hp = (const float*)d_in[5];
    float* out = (float*)d_out;

    dim3 gProj(E_ / 128, (B_ * S_) / 128, 2);
    proj_kernel<<<gProj, 256>>>(x, Wq, bq, Wv, bv);

    bucket_kernel<<<(B_ * H_ * S_) / 256, 256>>>(hp);

    const size_t attnSmem = (size_t)(4 * 64 * 68) * sizeof(float)
                          + 128 * sizeof(int);
    cudaFuncSetAttribute(attn_kernel,
                         cudaFuncAttributeMaxDynamicSharedMemorySize,
                         (int)attnSmem);
    attn_kernel<<<dim3(S_ / 64, B_ * H_), 256, attnSmem>>>(out);
}

// round 3
// speedup vs baseline: 3.2919x; 1.9905x over previous
#include <cuda_runtime.h>
#include <cuda_bf16.h>
#include <math.h>
#include <stdint.h>

#define B_ 2
#define S_ 2048
#define E_ 1024
#define H_ 16
#define DH 64

// Scratch (device globals — no allocation allowed)
__device__ float g_Q[(size_t)B_ * H_ * S_ * DH];            // fp32 q for buckets
__device__ __nv_bfloat16 g_Qh[(size_t)B_ * H_ * S_ * DH];
__device__ __nv_bfloat16 g_Ql[(size_t)B_ * H_ * S_ * DH];
__device__ __nv_bfloat16 g_Vh[(size_t)B_ * H_ * S_ * DH];
__device__ __nv_bfloat16 g_Vl[(size_t)B_ * H_ * S_ * DH];
__device__ int   g_bkt[B_ * H_ * S_];

typedef unsigned long long u64;
union F2 { u64 u; float2 f; };

__device__ __forceinline__ u64 dup2(float x) {
    u64 r; asm("mov.b64 %0,{%1,%1};" : "=l"(r) : "f"(x)); return r;
}
__device__ __forceinline__ void fma2(u64& d, u64 a, u64 b) {
    asm("fma.rn.f32x2 %0,%1,%2,%3;" : "=l"(d) : "l"(a), "l"(b), "l"(d));
}

// ---------------------------------------------------------------------------
// Projection GEMM (fp32, f32x2 FMA) — unchanged math; epilogue also emits
// bf16 hi/lo splits for the tensor-core attention.
// ---------------------------------------------------------------------------
__global__ __launch_bounds__(256, 2)
void proj_kernel(const float* __restrict__ x,
                 const float* __restrict__ Wq, const float* __restrict__ bq,
                 const float* __restrict__ Wv, const float* __restrict__ bv)
{
    const float* W    = blockIdx.z ? Wv : Wq;
    const float* bias = blockIdx.z ? bv : bq;

    __shared__ float At[16][132];
    __shared__ float Bt[16][132];

    const int tid = threadIdx.x;
    const int tn = tid & 15, tm = tid >> 4;
    const int m0 = blockIdx.y << 7;
    const int n0 = blockIdx.x << 7;

    u64 acc[4][8];
#pragma unroll
    for (int p = 0; p < 4; p++)
#pragma unroll
        for (int j = 0; j < 8; j++) acc[p][j] = 0ull;

    for (int k0 = 0; k0 < E_; k0 += 16) {
#pragma unroll
        for (int it = 0; it < 2; it++) {
            int idx = it * 256 + tid;
            int row = idx >> 2;
            int c = (idx & 3) << 2;
            float4 av = *(const float4*)(x + (size_t)(m0 + row) * E_ + k0 + c);
            At[c + 0][row] = av.x; At[c + 1][row] = av.y;
            At[c + 2][row] = av.z; At[c + 3][row] = av.w;
            float4 bw = *(const float4*)(W + (size_t)(n0 + row) * E_ + k0 + c);
            Bt[c + 0][row] = bw.x; Bt[c + 1][row] = bw.y;
            Bt[c + 2][row] = bw.z; Bt[c + 3][row] = bw.w;
        }
        __syncthreads();

#pragma unroll
        for (int k = 0; k < 16; k++) {
            ulonglong2 a01 = *(const ulonglong2*)&At[k][tm * 8];
            ulonglong2 a23 = *(const ulonglong2*)&At[k][tm * 8 + 4];
            float4 b0 = *(const float4*)&Bt[k][tn * 8];
            float4 b1 = *(const float4*)&Bt[k][tn * 8 + 4];
            u64 bd[8];
            bd[0] = dup2(b0.x); bd[1] = dup2(b0.y);
            bd[2] = dup2(b0.z); bd[3] = dup2(b0.w);
            bd[4] = dup2(b1.x); bd[5] = dup2(b1.y);
            bd[6] = dup2(b1.z); bd[7] = dup2(b1.w);
            u64 ap[4] = {a01.x, a01.y, a23.x, a23.y};
#pragma unroll
            for (int p = 0; p < 4; p++)
#pragma unroll
                for (int j = 0; j < 8; j++)
                    fma2(acc[p][j], ap[p], bd[j]);
        }
        __syncthreads();
    }

    const int nb = n0 + tn * 8;
    const int h = nb >> 6;
    const int d = nb & 63;
    float bi[8];
#pragma unroll
    for (int j = 0; j < 8; j++) bi[j] = bias[nb + j];

    __nv_bfloat16* Hh = blockIdx.z ? g_Vh : g_Qh;
    __nv_bfloat16* Hl = blockIdx.z ? g_Vl : g_Ql;

#pragma unroll
    for (int p = 0; p < 4; p++) {
#pragma unroll
        for (int sub = 0; sub < 2; sub++) {
            int m = m0 + tm * 8 + 2 * p + sub;
            int b = m >> 11, s = m & (S_ - 1);
            size_t off = (((size_t)(b * H_ + h)) * S_ + s) * DH + d;
            float v[8];
#pragma unroll
            for (int j = 0; j < 8; j++) {
                F2 u; u.u = acc[p][j];
                v[j] = (sub ? u.f.y : u.f.x) + bi[j];
            }
            if (blockIdx.z == 0) {
                *(float4*)(g_Q + off)     = make_float4(v[0], v[1], v[2], v[3]);
                *(float4*)(g_Q + off + 4) = make_float4(v[4], v[5], v[6], v[7]);
            }
            __align__(16) __nv_bfloat16 hi8[8];
            __align__(16) __nv_bfloat16 lo8[8];
#pragma unroll
            for (int j = 0; j < 8; j++) {
                hi8[j] = __float2bfloat16(v[j]);
                lo8[j] = __float2bfloat16(v[j] - __bfloat162float(hi8[j]));
            }
            *(uint4*)(Hh + off) = *(const uint4*)hi8;
            *(uint4*)(Hl + off) = *(const uint4*)lo8;
        }
    }
}

// ---------------------------------------------------------------------------
// LSH buckets from fp32 q (bit-exact signs).
// ---------------------------------------------------------------------------
__global__ __launch_bounds__(256)
void bucket_kernel(const float* __restrict__ hp)
{
    __shared__ float shp[65 * 6];
    for (int i = threadIdx.x; i < 65 * 6; i += 256) shp[i] = hp[i];
    __syncthreads();

    int idx = blockIdx.x * 256 + threadIdx.x;
    const float* q = g_Q + (size_t)idx * DH;
    float proj[6];
#pragma unroll
    for (int n = 0; n < 6; n++) proj[n] = shp[64 * 6 + n];
    for (int d = 0; d < DH; d++) {
        float qd = q[d];
#pragma unroll
        for (int n = 0; n < 6; n++) proj[n] = fmaf(qd, shp[d * 6 + n], proj[n]);
    }
    int bucket = 0;
#pragma unroll
    for (int n = 0; n < 6; n++) if (proj[n] >= 0.f) bucket |= (1 << n);
    g_bkt[idx] = bucket;
}

// ---------------------------------------------------------------------------
// Tensor-core flash attention (mma.sync m16n8k16 bf16, x3 split).
//   logit = (q.k) * (63/32 or 62/32)
// CTA: 128 threads (4 warps), s-tile 64 (16 rows/warp), t-tiles of 64.
// ---------------------------------------------------------------------------
#define RS 72           // smem row stride in bf16 elems (144 B)
#define RSB 144         // bytes

__device__ __forceinline__ void ldsm4(uint32_t* r, uint32_t a) {
    asm volatile("ldmatrix.sync.aligned.m8n8.x4.shared.b16 {%0,%1,%2,%3},[%4];"
                 : "=r"(r[0]), "=r"(r[1]), "=r"(r[2]), "=r"(r[3]) : "r"(a));
}
__device__ __forceinline__ void ldsm4t(uint32_t* r, uint32_t a) {
    asm volatile("ldmatrix.sync.aligned.m8n8.x4.trans.shared.b16 {%0,%1,%2,%3},[%4];"
                 : "=r"(r[0]), "=r"(r[1]), "=r"(r[2]), "=r"(r[3]) : "r"(a));
}
__device__ __forceinline__ void mma16816(float* c, const uint32_t* a,
                                         uint32_t b0, uint32_t b1) {
    asm volatile(
        "mma.sync.aligned.m16n8k16.row.col.f32.bf16.bf16.f32 "
        "{%0,%1,%2,%3},{%4,%5,%6,%7},{%8,%9},{%0,%1,%2,%3};"
        : "+f"(c[0]), "+f"(c[1]), "+f"(c[2]), "+f"(c[3])
        : "r"(a[0]), "r"(a[1]), "r"(a[2]), "r"(a[3]), "r"(b0), "r"(b1));
}
__device__ __forceinline__ uint32_t packbf(float lo, float hi) {
    uint32_t r; asm("cvt.rn.bf16x2.f32 %0,%1,%2;" : "=r"(r) : "f"(hi), "f"(lo));
    return r;
}

__global__ __launch_bounds__(128, 3)
void attn_kernel(float* __restrict__ out)
{
    __shared__ __align__(16) __nv_bfloat16 sKh[64 * RS];
    __shared__ __align__(16) __nv_bfloat16 sKl[64 * RS];
    __shared__ __align__(16) __nv_bfloat16 sVh[64 * RS];
    __shared__ __align__(16) __nv_bfloat16 sVl[64 * RS];
    __shared__ int bksm[64];

    const int tid = threadIdx.x;
    const int wid = tid >> 5, lane = tid & 31;
    const int qid = lane >> 2;          // row within warp's 16 (and +8)
    const int l2  = lane & 3;
    const int sel = lane >> 3, l7 = lane & 7;

    const int bh = blockIdx.y;
    const int b = bh >> 4, h = bh & 15;
    const int s0 = blockIdx.x << 6;
    const __nv_bfloat16* Qh_g = g_Qh + (size_t)bh * S_ * DH;
    const __nv_bfloat16* Ql_g = g_Ql + (size_t)bh * S_ * DH;
    const __nv_bfloat16* Vh_g = g_Vh + (size_t)bh * S_ * DH;
    const __nv_bfloat16* Vl_g = g_Vl + (size_t)bh * S_ * DH;
    const int* bkp = g_bkt + bh * S_;

    const uint32_t aKh = (uint32_t)__cvta_generic_to_shared(sKh);
    const uint32_t aKl = (uint32_t)__cvta_generic_to_shared(sKl);
    const uint32_t aVh = (uint32_t)__cvta_generic_to_shared(sVh);
    const uint32_t aVl = (uint32_t)__cvta_generic_to_shared(sVl);

    // ---- stage Q tile into sKh/sKl, load A fragments ----
#pragma unroll
    for (int i = tid; i < 512; i += 128) {
        int r = i >> 3, c = (i & 7) << 3;
        *(uint4*)(sKh + r * RS + c) = *(const uint4*)(Qh_g + (size_t)(s0 + r) * DH + c);
        *(uint4*)(sKl + r * RS + c) = *(const uint4*)(Ql_g + (size_t)(s0 + r) * DH + c);
    }
    __syncthreads();

    uint32_t Ah[4][4], Al[4][4];
    {
        uint32_t qoff = (uint32_t)((wid * 16 + (sel & 1) * 8 + l7) * RSB + (sel >> 1) * 16);
#pragma unroll
        for (int u = 0; u < 4; u++) {
            ldsm4(Ah[u], aKh + qoff + u * 32);
            ldsm4(Al[u], aKl + qoff + u * 32);
        }
    }
    const int bq0 = bkp[s0 + wid * 16 + qid];
    const int bq1 = bkp[s0 + wid * 16 + qid + 8];
    __syncthreads();   // done reading Q staging before K overwrites

    float O[8][4];
#pragma unroll
    for (int j = 0; j < 8; j++)
#pragma unroll
        for (int k = 0; k < 4; k++) O[j][k] = 0.f;
    float m0 = -INFINITY, m1 = -INFINITY, l0 = 0.f, l1 = 0.f;

    // per-lane ldmatrix bases
    const uint32_t kb_base = ((sel < 2) ? aKh : aKl) + l7 * RSB + (sel & 1) * 16;
    const uint32_t vb_base = ((sel < 2) ? aVh : aVl) + (l7 + (sel & 1) * 8) * RSB;

    for (int t0 = 0; t0 < S_; t0 += 64) {
        // ---- load K/V hi+lo tiles ----
#pragma unroll
        for (int i = tid; i < 512; i += 128) {
            int r = i >> 3, c = (i & 7) << 3;
            size_t go = (size_t)(t0 + r) * DH + c;
            *(uint4*)(sKh + r * RS + c) = *(const uint4*)(Qh_g + go);
            *(uint4*)(sKl + r * RS + c) = *(const uint4*)(Ql_g + go);
            *(uint4*)(sVh + r * RS + c) = *(const uint4*)(Vh_g + go);
            *(uint4*)(sVl + r * RS + c) = *(const uint4*)(Vl_g + go);
        }
        if (tid < 64) bksm[tid] = bkp[t0 + tid];
        __syncthreads();

        // ---- S = Q K^T (x3 split) ----
        float C[8][4];
#pragma unroll
        for (int j = 0; j < 8; j++)
#pragma unroll
            for (int k = 0; k < 4; k++) C[j][k] = 0.f;

#pragma unroll
        for (int j = 0; j < 8; j++) {
#pragma unroll
            for (int u = 0; u < 4; u++) {
                uint32_t kb[4];
                ldsm4(kb, kb_base + j * (8 * RSB) + u * 32);
                mma16816(C[j], Ah[u], kb[0], kb[1]);   // qh*kh
                mma16816(C[j], Al[u], kb[0], kb[1]);   // ql*kh
                mma16816(C[j], Ah[u], kb[2], kb[3]);   // qh*kl
            }
        }

        // ---- coeff + online softmax ----
        float rmax0 = -INFINITY, rmax1 = -INFINITY;
#pragma unroll
        for (int j = 0; j < 8; j++) {
            int tcol = 8 * j + 2 * l2;
            int bk0 = bksm[tcol], bk1 = bksm[tcol + 1];
            float cf00 = (bq0 == bk0) ? 1.96875f : 1.9375f;
            float cf01 = (bq0 == bk1) ? 1.96875f : 1.9375f;
            float cf10 = (bq1 == bk0) ? 1.96875f : 1.9375f;
            float cf11 = (bq1 == bk1) ? 1.96875f : 1.9375f;
            C[j][0] *= cf00; C[j][1] *= cf01;
            C[j][2] *= cf10; C[j][3] *= cf11;
            rmax0 = fmaxf(rmax0, fmaxf(C[j][0], C[j][1]));
            rmax1 = fmaxf(rmax1, fmaxf(C[j][2], C[j][3]));
        }
        rmax0 = fmaxf(rmax0, __shfl_xor_sync(0xffffffffu, rmax0, 1));
        rmax0 = fmaxf(rmax0, __shfl_xor_sync(0xffffffffu, rmax0, 2));
        rmax1 = fmaxf(rmax1, __shfl_xor_sync(0xffffffffu, rmax1, 1));
        rmax1 = fmaxf(rmax1, __shfl_xor_sync(0xffffffffu, rmax1, 2));

        float mn0 = fmaxf(m0, rmax0);
        float mn1 = fmaxf(m1, rmax1);
        float corr0 = __expf(m0 - mn0);
        float corr1 = __expf(m1 - mn1);
        m0 = mn0; m1 = mn1;

        float sum0 = 0.f, sum1 = 0.f;
#pragma unroll
        for (int j = 0; j < 8; j++) {
            C[j][0] = __expf(C[j][0] - mn0);
            C[j][1] = __expf(C[j][1] - mn0);
            C[j][2] = __expf(C[j][2] - mn1);
            C[j][3] = __expf(C[j][3] - mn1);
            sum0 += C[j][0] + C[j][1];
            sum1 += C[j][2] + C[j][3];
        }
        sum0 += __shfl_xor_sync(0xffffffffu, sum0, 1);
        sum0 += __shfl_xor_sync(0xffffffffu, sum0, 2);
        sum1 += __shfl_xor_sync(0xffffffffu, sum1, 1);
        sum1 += __shfl_xor_sync(0xffffffffu, sum1, 2);
        l0 = l0 * corr0 + sum0;
        l1 = l1 * corr1 + sum1;

#pragma unroll
        for (int j = 0; j < 8; j++) {
            O[j][0] *= corr0; O[j][1] *= corr0;
            O[j][2] *= corr1; O[j][3] *= corr1;
        }

        // ---- O += P V (x3 split) ----
#pragma unroll
        for (int u = 0; u < 4; u++) {
            // P fragments (A-layout) from C[2u], C[2u+1]
            uint32_t ph[4], pl[4];
#pragma unroll
            for (int half = 0; half < 2; half++) {
                const float* cc = C[2 * u + half];
                uint32_t h0 = packbf(cc[0], cc[1]);
                uint32_t h1 = packbf(cc[2], cc[3]);
                float r00 = cc[0] - __uint_as_float(h0 << 16);
                float r01 = cc[1] - __uint_as_float(h0 & 0xFFFF0000u);
                float r10 = cc[2] - __uint_as_float(h1 << 16);
                float r11 = cc[3] - __uint_as_float(h1 & 0xFFFF0000u);
                ph[2 * half]     = h0;
                ph[2 * half + 1] = h1;
                pl[2 * half]     = packbf(r00, r01);
                pl[2 * half + 1] = packbf(r10, r11);
            }
#pragma unroll
            for (int jd = 0; jd < 8; jd++) {
                uint32_t vb[4];
                ldsm4t(vb, vb_base + u * (16 * RSB) + jd * 16);
                mma16816(O[jd], ph, vb[0], vb[1]);   // ph*vh
                mma16816(O[jd], pl, vb[0], vb[1]);   // pl*vh
                mma16816(O[jd], ph, vb[2], vb[3]);   // ph*vl
            }
        }
        __syncthreads();   // all warps done with K/V before next overwrite
    }

    // ---- normalize + store out[b, s, h, d] ----
    const float inv0 = 1.f / l0;
    const float inv1 = 1.f / l1;
    const int srow0 = s0 + wid * 16 + qid;
    const int srow1 = srow0 + 8;
#pragma unroll
    for (int jd = 0; jd < 8; jd++) {
        int d = 8 * jd + 2 * l2;
        float* p0 = out + (((size_t)(b * S_ + srow0)) * H_ + h) * DH + d;
        float* p1 = out + (((size_t)(b * S_ + srow1)) * H_ + h) * DH + d;
        *(float2*)p0 = make_float2(O[jd][0] * inv0, O[jd][1] * inv0);
        *(float2*)p1 = make_float2(O[jd][2] * inv1, O[jd][3] * inv1);
    }
}

// ---------------------------------------------------------------------------
extern "C" void kernel_launch(void* const* d_in, const int* in_sizes, int n_in,
                              void* d_out, int out_size)
{
    const float* x  = (const float*)d_in[0];
    const float* Wq = (const float*)d_in[1];
    const float* bq = (const float*)d_in[2];
    const float* Wv = (const float*)d_in[3];
    const float* bv = (const float*)d_in[4];
    const float* hp = (const float*)d_in[5];
    float* out = (float*)d_out;

    dim3 gProj(E_ / 128, (B_ * S_) / 128, 2);
    proj_kernel<<<gProj, 256>>>(x, Wq, bq, Wv, bv);

    bucket_kernel<<<(B_ * H_ * S_) / 256, 256>>>(hp);

    attn_kernel<<<dim3(S_ / 64, B_ * H_), 128>>>(out);
}

// round 4
// speedup vs baseline: 4.2030x; 1.2768x over previous
#include <cuda_runtime.h>
#include <cuda_bf16.h>
#include <math.h>
#include <stdint.h>

#define B_ 2
#define S_ 2048
#define E_ 1024
#define H_ 16
#define DH 64

// Scratch (device globals — no allocation allowed)
__device__ __nv_bfloat16 g_xh[(size_t)B_ * S_ * E_];
__device__ __nv_bfloat16 g_xl[(size_t)B_ * S_ * E_];
__device__ __nv_bfloat16 g_Wqh[(size_t)E_ * E_];
__device__ __nv_bfloat16 g_Wql[(size_t)E_ * E_];
__device__ __nv_bfloat16 g_Wvh[(size_t)E_ * E_];
__device__ __nv_bfloat16 g_Wvl[(size_t)E_ * E_];
__device__ __nv_bfloat16 g_Qh[(size_t)B_ * H_ * S_ * DH];
__device__ __nv_bfloat16 g_Ql[(size_t)B_ * H_ * S_ * DH];
__device__ __nv_bfloat16 g_Vh[(size_t)B_ * H_ * S_ * DH];
__device__ __nv_bfloat16 g_Vl[(size_t)B_ * H_ * S_ * DH];
__device__ float g_Whp[(size_t)E_ * 96];     // [e][h*6+n]
__device__ float g_cbias[96];
__device__ int   g_bkt[B_ * H_ * S_];

typedef unsigned long long u64;
union F2 { u64 u; float2 f; };

__device__ __forceinline__ u64 dup2(float x) {
    u64 r; asm("mov.b64 %0,{%1,%1};" : "=l"(r) : "f"(x)); return r;
}
__device__ __forceinline__ void fma2(u64& d, u64 a, u64 b) {
    asm("fma.rn.f32x2 %0,%1,%2,%3;" : "=l"(d) : "l"(a), "l"(b), "l"(d));
}
__device__ __forceinline__ void ldsm4(uint32_t* r, uint32_t a) {
    asm volatile("ldmatrix.sync.aligned.m8n8.x4.shared.b16 {%0,%1,%2,%3},[%4];"
                 : "=r"(r[0]), "=r"(r[1]), "=r"(r[2]), "=r"(r[3]) : "r"(a));
}
__device__ __forceinline__ void ldsm4t(uint32_t* r, uint32_t a) {
    asm volatile("ldmatrix.sync.aligned.m8n8.x4.trans.shared.b16 {%0,%1,%2,%3},[%4];"
                 : "=r"(r[0]), "=r"(r[1]), "=r"(r[2]), "=r"(r[3]) : "r"(a));
}
__device__ __forceinline__ void mma16816(float* c, const uint32_t* a,
                                         uint32_t b0, uint32_t b1) {
    asm volatile(
        "mma.sync.aligned.m16n8k16.row.col.f32.bf16.bf16.f32 "
        "{%0,%1,%2,%3},{%4,%5,%6,%7},{%8,%9},{%0,%1,%2,%3};"
        : "+f"(c[0]), "+f"(c[1]), "+f"(c[2]), "+f"(c[3])
        : "r"(a[0]), "r"(a[1]), "r"(a[2]), "r"(a[3]), "r"(b0), "r"(b1));
}
__device__ __forceinline__ uint32_t packbf(float lo, float hi) {
    uint32_t r; asm("cvt.rn.bf16x2.f32 %0,%1,%2;" : "=r"(r) : "f"(hi), "f"(lo));
    return r;
}

// ---------------------------------------------------------------------------
// Split x, Wq, Wv into bf16 hi/lo pairs. 4 floats per thread.
// ---------------------------------------------------------------------------
__global__ __launch_bounds__(256)
void split_kernel(const float* __restrict__ x, const float* __restrict__ Wq,
                  const float* __restrict__ Wv)
{
    size_t idx4 = (size_t)blockIdx.x * 256 + threadIdx.x;
    size_t flat = idx4 * 4;
    const float* src; __nv_bfloat16* dh; __nv_bfloat16* dl; size_t off;
    const size_t NX = (size_t)B_ * S_ * E_;       // 4M
    const size_t NW = (size_t)E_ * E_;            // 1M
    if (flat < NX)            { src = x;  dh = g_xh;  dl = g_xl;  off = flat; }
    else if (flat < NX + NW)  { src = Wq; dh = g_Wqh; dl = g_Wql; off = flat - NX; }
    else                      { src = Wv; dh = g_Wvh; dl = g_Wvl; off = flat - NX - NW; }

    float4 v = *(const float4*)(src + off);
    float vv[4] = {v.x, v.y, v.z, v.w};
    __align__(8) __nv_bfloat16 hi[4], lo[4];
#pragma unroll
    for (int j = 0; j < 4; j++) {
        hi[j] = __float2bfloat16(vv[j]);
        lo[j] = __float2bfloat16(vv[j] - __bfloat162float(hi[j]));
    }
    *(uint2*)(dh + off) = *(const uint2*)hi;
    *(uint2*)(dl + off) = *(const uint2*)lo;
}

// ---------------------------------------------------------------------------
// Whp[e][h*6+n] = sum_d Wq[h*64+d][e] * hp[d][n]  ;  cbias[hn] too.
// grid (4, 96), 256 threads: tid -> e, blockIdx.y -> hn.
// ---------------------------------------------------------------------------
__global__ __launch_bounds__(256)
void whp_kernel(const float* __restrict__ Wq, const float* __restrict__ bq,
                const float* __restrict__ hp)
{
    const int hn = blockIdx.y;
    const int h = hn / 6, n = hn % 6;
    const int e = blockIdx.x * 256 + threadIdx.x;
    float acc = 0.f;
#pragma unroll 8
    for (int d = 0; d < 64; d++)
        acc = fmaf(Wq[(size_t)(h * 64 + d) * E_ + e], __ldg(hp + d * 6 + n), acc);
    g_Whp[(size_t)e * 96 + hn] = acc;
    if (blockIdx.x == 0 && threadIdx.x == 0) {
        float cb = hp[64 * 6 + n];
        for (int d = 0; d < 64; d++)
            cb = fmaf(bq[h * 64 + d], hp[d * 6 + n], cb);
        g_cbias[hn] = cb;
    }
}

// ---------------------------------------------------------------------------
// Bucket GEMM: proj[m][hn] = sum_e x[m][e]*Whp[e][hn] + cbias[hn]; sign bits.
// grid 64 (64 rows each), 256 threads, f32x2. smem: sx[128k][68] + sw[128k][96].
// ---------------------------------------------------------------------------
#define BK_B 128
__global__ __launch_bounds__(256)
void bucket_kernel(const float* __restrict__ x)
{
    extern __shared__ float bsm[];
    float* sx = bsm;                 // [BK_B][68]  (transposed x chunk)
    float* sw = bsm + BK_B * 68;     // [BK_B][96]

    const int tid = threadIdx.x;
    const int tx = tid & 31;         // cols tx, tx+32, tx+64
    const int ty = tid >> 5;         // rows 8*ty .. 8*ty+7
    const int m0 = blockIdx.x * 64;

    u64 acc[4][3];
#pragma unroll
    for (int p = 0; p < 4; p++)
#pragma unroll
        for (int c = 0; c < 3; c++) acc[p][c] = dup2(g_cbias[tx + 32 * c]);

    for (int k0 = 0; k0 < E_; k0 += BK_B) {
        // stage x transposed: rows m0..m0+63, cols k0..k0+127
#pragma unroll
        for (int it = 0; it < 8; it++) {
            int idx = it * 256 + tid;          // 0..2047
            int r = idx >> 5;
            int c4 = (idx & 31) << 2;
            float4 v = *(const float4*)(x + (size_t)(m0 + r) * E_ + k0 + c4);
            sx[(c4 + 0) * 68 + r] = v.x; sx[(c4 + 1) * 68 + r] = v.y;
            sx[(c4 + 2) * 68 + r] = v.z; sx[(c4 + 3) * 68 + r] = v.w;
        }
        // stage Whp chunk: linear copy [128][96]
#pragma unroll
        for (int it = 0; it < 12; it++) {
            int u4 = it * 256 + tid;           // 0..3071 uint4
            *(uint4*)(sw + u4 * 4) =
                *(const uint4*)(g_Whp + (size_t)k0 * 96 + u4 * 4);
        }
        __syncthreads();

#pragma unroll 4
        for (int k = 0; k < BK_B; k++) {
            ulonglong2 x01 = *(const ulonglong2*)(sx + k * 68 + 8 * ty);
            ulonglong2 x23 = *(const ulonglong2*)(sx + k * 68 + 8 * ty + 4);
            u64 xp[4] = {x01.x, x01.y, x23.x, x23.y};
            u64 w0 = dup2(sw[k * 96 + tx]);
            u64 w1 = dup2(sw[k * 96 + tx + 32]);
            u64 w2 = dup2(sw[k * 96 + tx + 64]);
#pragma unroll
            for (int p = 0; p < 4; p++) {
                fma2(acc[p][0], xp[p], w0);
                fma2(acc[p][1], xp[p], w1);
                fma2(acc[p][2], xp[p], w2);
            }
        }
        __syncthreads();
    }

    // write proj to smem (reuse sx region), then assemble buckets
    float* sproj = sx;               // [64][96]
#pragma unroll
    for (int p = 0; p < 4; p++) {
#pragma unroll
        for (int c = 0; c < 3; c++) {
            F2 u; u.u = acc[p][c];
            sproj[(8 * ty + 2 * p) * 96 + tx + 32 * c]     = u.f.x;
            sproj[(8 * ty + 2 * p + 1) * 96 + tx + 32 * c] = u.f.y;
        }
    }
    __syncthreads();

#pragma unroll
    for (int u = 0; u < 4; u++) {
        int o = u * 256 + tid;       // 0..1023 = 64 rows x 16 heads
        int row = o >> 4, h = o & 15;
        int bucket = 0;
#pragma unroll
        for (int n = 0; n < 6; n++)
            if (sproj[row * 96 + h * 6 + n] >= 0.f) bucket |= (1 << n);
        int m = m0 + row;
        int b = m >> 11, s = m & (S_ - 1);
        g_bkt[(b * H_ + h) * S_ + s] = bucket;
    }
}

// ---------------------------------------------------------------------------
// Tensor-core projection GEMM (bf16 x3): C = x @ W^T + bias -> hi/lo splits.
// CTA 128x128, BK=32, 8 warps (4m x 2n), warp tile 32x64.
// grid (8, 32, 2): z=0 -> Q, z=1 -> V.
// ---------------------------------------------------------------------------
#define PST 40   // smem row stride (bf16 elems), 80 bytes
__global__ __launch_bounds__(256, 2)
void proj_tc_kernel(const float* __restrict__ bq, const float* __restrict__ bv)
{
    __shared__ __align__(16) __nv_bfloat16 sAh[128 * PST];
    __shared__ __align__(16) __nv_bfloat16 sAl[128 * PST];
    __shared__ __align__(16) __nv_bfloat16 sBh[128 * PST];
    __shared__ __align__(16) __nv_bfloat16 sBl[128 * PST];

    const int z = blockIdx.z;
    const __nv_bfloat16* Bh_g = z ? g_Wvh : g_Wqh;
    const __nv_bfloat16* Bl_g = z ? g_Wvl : g_Wql;
    const float* bias = z ? bv : bq;
    __nv_bfloat16* Hh = z ? g_Vh : g_Qh;
    __nv_bfloat16* Hl = z ? g_Vl : g_Ql;

    const int tid = threadIdx.x;
    const int wid = tid >> 5, lane = tid & 31;
    const int qid = lane >> 2, l2 = lane & 3;
    const int sel = lane >> 3, l7 = lane & 7;
    const int wm = wid & 3, wn = wid >> 2;
    const int m0 = blockIdx.y << 7;
    const int n0 = blockIdx.x << 7;

    const uint32_t aAh = (uint32_t)__cvta_generic_to_shared(sAh);
    const uint32_t aAl = (uint32_t)__cvta_generic_to_shared(sAl);
    const uint32_t aBh = (uint32_t)__cvta_generic_to_shared(sBh);
    const uint32_t aBl = (uint32_t)__cvta_generic_to_shared(sBl);

    float C[2][8][4];
#pragma unroll
    for (int a = 0; a < 2; a++)
#pragma unroll
        for (int j = 0; j < 8; j++)
#pragma unroll
            for (int t = 0; t < 4; t++) C[a][j][t] = 0.f;

    const uint32_t aoff = (uint32_t)((wm * 32 + (sel & 1) * 8 + l7) * (PST * 2)
                                     + (sel >> 1) * 16);
    const uint32_t bbase = ((sel < 2) ? aBh : aBl)
                         + (wn * 64 + l7) * (PST * 2) + (sel & 1) * 16;

    for (int k0 = 0; k0 < E_; k0 += 32) {
#pragma unroll
        for (int p = 0; p < 2; p++) {
            int idx = tid * 2 + p;          // 0..511
            int r = idx >> 2;
            int cu = (idx & 3) << 3;        // bf16 col offset
            size_t gx = (size_t)(m0 + r) * E_ + k0 + cu;
            size_t gw = (size_t)(n0 + r) * E_ + k0 + cu;
            *(uint4*)(sAh + r * PST + cu) = *(const uint4*)(g_xh + gx);
            *(uint4*)(sAl + r * PST + cu) = *(const uint4*)(g_xl + gx);
            *(uint4*)(sBh + r * PST + cu) = *(const uint4*)(Bh_g + gw);
            *(uint4*)(sBl + r * PST + cu) = *(const uint4*)(Bl_g + gw);
        }
        __syncthreads();

#pragma unroll
        for (int kk = 0; kk < 2; kk++) {
            uint32_t Ahf[2][4], Alf[2][4];
#pragma unroll
            for (int a = 0; a < 2; a++) {
                uint32_t ra = aoff + a * 16 * (PST * 2) + kk * 32;
                ldsm4(Ahf[a], aAh + ra);
                ldsm4(Alf[a], aAl + ra);
            }
#pragma unroll
            for (int j = 0; j < 8; j++) {
                uint32_t bb[4];
                ldsm4(bb, bbase + j * 8 * (PST * 2) + kk * 32);
#pragma unroll
                for (int a = 0; a < 2; a++) {
                    mma16816(C[a][j], Ahf[a], bb[0], bb[1]);
                    mma16816(C[a][j], Alf[a], bb[0], bb[1]);
                    mma16816(C[a][j], Ahf[a], bb[2], bb[3]);
                }
            }
        }
        __syncthreads();
    }

    // epilogue: + bias (fp32), split hi/lo, scatter to [B,H,S,Dh]
#pragma unroll
    for (int a = 0; a < 2; a++) {
        int mrow = m0 + wm * 32 + a * 16 + qid;
#pragma unroll
        for (int j = 0; j < 8; j++) {
            int n = n0 + wn * 64 + j * 8 + 2 * l2;
            int h = n >> 6, d = n & 63;
            float b0 = bias[n], b1 = bias[n + 1];
#pragma unroll
            for (int half = 0; half < 2; half++) {
                int m = mrow + half * 8;
                int b = m >> 11, s = m & (S_ - 1);
                size_t off = (((size_t)(b * H_ + h)) * S_ + s) * DH + d;
                float v0 = C[a][j][2 * half + 0] + b0;
                float v1 = C[a][j][2 * half + 1] + b1;
                uint32_t hi = packbf(v0, v1);
                float l0 = v0 - __uint_as_float(hi << 16);
                float l1 = v1 - __uint_as_float(hi & 0xFFFF0000u);
                *(uint32_t*)(Hh + off) = hi;
                *(uint32_t*)(Hl + off) = packbf(l0, l1);
            }
        }
    }
}

// ---------------------------------------------------------------------------
// Tensor-core flash attention (unchanged from R3).
// ---------------------------------------------------------------------------
#define RS 72
#define RSB 144

__global__ __launch_bounds__(128, 3)
void attn_kernel(float* __restrict__ out)
{
    __shared__ __align__(16) __nv_bfloat16 sKh[64 * RS];
    __shared__ __align__(16) __nv_bfloat16 sKl[64 * RS];
    __shared__ __align__(16) __nv_bfloat16 sVh[64 * RS];
    __shared__ __align__(16) __nv_bfloat16 sVl[64 * RS];
    __shared__ int bksm[64];

    const int tid = threadIdx.x;
    const int wid = tid >> 5, lane = tid & 31;
    const int qid = lane >> 2;
    const int l2  = lane & 3;
    const int sel = lane >> 3, l7 = lane & 7;

    const int bh = blockIdx.y;
    const int b = bh >> 4, h = bh & 15;
    const int s0 = blockIdx.x << 6;
    const __nv_bfloat16* Qh_g = g_Qh + (size_t)bh * S_ * DH;
    const __nv_bfloat16* Ql_g = g_Ql + (size_t)bh * S_ * DH;
    const __nv_bfloat16* Vh_g = g_Vh + (size_t)bh * S_ * DH;
    const __nv_bfloat16* Vl_g = g_Vl + (size_t)bh * S_ * DH;
    const int* bkp = g_bkt + bh * S_;

    const uint32_t aKh = (uint32_t)__cvta_generic_to_shared(sKh);
    const uint32_t aKl = (uint32_t)__cvta_generic_to_shared(sKl);
    const uint32_t aVh = (uint32_t)__cvta_generic_to_shared(sVh);
    const uint32_t aVl = (uint32_t)__cvta_generic_to_shared(sVl);

#pragma unroll
    for (int i = tid; i < 512; i += 128) {
        int r = i >> 3, c = (i & 7) << 3;
        *(uint4*)(sKh + r * RS + c) = *(const uint4*)(Qh_g + (size_t)(s0 + r) * DH + c);
        *(uint4*)(sKl + r * RS + c) = *(const uint4*)(Ql_g + (size_t)(s0 + r) * DH + c);
    }
    __syncthreads();

    uint32_t Ah[4][4], Al[4][4];
    {
        uint32_t qoff = (uint32_t)((wid * 16 + (sel & 1) * 8 + l7) * RSB + (sel >> 1) * 16);
#pragma unroll
        for (int u = 0; u < 4; u++) {
            ldsm4(Ah[u], aKh + qoff + u * 32);
            ldsm4(Al[u], aKl + qoff + u * 32);
        }
    }
    const int bq0 = bkp[s0 + wid * 16 + qid];
    const int bq1 = bkp[s0 + wid * 16 + qid + 8];
    __syncthreads();

    float O[8][4];
#pragma unroll
    for (int j = 0; j < 8; j++)
#pragma unroll
        for (int k = 0; k < 4; k++) O[j][k] = 0.f;
    float m0 = -INFINITY, m1 = -INFINITY, l0 = 0.f, l1 = 0.f;

    const uint32_t kb_base = ((sel < 2) ? aKh : aKl) + l7 * RSB + (sel & 1) * 16;
    const uint32_t vb_base = ((sel < 2) ? aVh : aVl) + (l7 + (sel & 1) * 8) * RSB;

    for (int t0 = 0; t0 < S_; t0 += 64) {
#pragma unroll
        for (int i = tid; i < 512; i += 128) {
            int r = i >> 3, c = (i & 7) << 3;
            size_t go = (size_t)(t0 + r) * DH + c;
            *(uint4*)(sKh + r * RS + c) = *(const uint4*)(Qh_g + go);
            *(uint4*)(sKl + r * RS + c) = *(const uint4*)(Ql_g + go);
            *(uint4*)(sVh + r * RS + c) = *(const uint4*)(Vh_g + go);
            *(uint4*)(sVl + r * RS + c) = *(const uint4*)(Vl_g + go);
        }
        if (tid < 64) bksm[tid] = bkp[t0 + tid];
        __syncthreads();

        float C[8][4];
#pragma unroll
        for (int j = 0; j < 8; j++)
#pragma unroll
            for (int k = 0; k < 4; k++) C[j][k] = 0.f;

#pragma unroll
        for (int j = 0; j < 8; j++) {
#pragma unroll
            for (int u = 0; u < 4; u++) {
                uint32_t kb[4];
                ldsm4(kb, kb_base + j * (8 * RSB) + u * 32);
                mma16816(C[j], Ah[u], kb[0], kb[1]);
                mma16816(C[j], Al[u], kb[0], kb[1]);
                mma16816(C[j], Ah[u], kb[2], kb[3]);
            }
        }

        float rmax0 = -INFINITY, rmax1 = -INFINITY;
#pragma unroll
        for (int j = 0; j < 8; j++) {
            int tcol = 8 * j + 2 * l2;
            int bk0 = bksm[tcol], bk1 = bksm[tcol + 1];
            float cf00 = (bq0 == bk0) ? 1.96875f : 1.9375f;
            float cf01 = (bq0 == bk1) ? 1.96875f : 1.9375f;
            float cf10 = (bq1 == bk0) ? 1.96875f : 1.9375f;
            float cf11 = (bq1 == bk1) ? 1.96875f : 1.9375f;
            C[j][0] *= cf00; C[j][1] *= cf01;
            C[j][2] *= cf10; C[j][3] *= cf11;
            rmax0 = fmaxf(rmax0, fmaxf(C[j][0], C[j][1]));
            rmax1 = fmaxf(rmax1, fmaxf(C[j][2], C[j][3]));
        }
        rmax0 = fmaxf(rmax0, __shfl_xor_sync(0xffffffffu, rmax0, 1));
        rmax0 = fmaxf(rmax0, __shfl_xor_sync(0xffffffffu, rmax0, 2));
        rmax1 = fmaxf(rmax1, __shfl_xor_sync(0xffffffffu, rmax1, 1));
        rmax1 = fmaxf(rmax1, __shfl_xor_sync(0xffffffffu, rmax1, 2));

        float mn0 = fmaxf(m0, rmax0);
        float mn1 = fmaxf(m1, rmax1);
        float corr0 = __expf(m0 - mn0);
        float corr1 = __expf(m1 - mn1);
        m0 = mn0; m1 = mn1;

        float sum0 = 0.f, sum1 = 0.f;
#pragma unroll
        for (int j = 0; j < 8; j++) {
            C[j][0] = __expf(C[j][0] - mn0);
            C[j][1] = __expf(C[j][1] - mn0);
            C[j][2] = __expf(C[j][2] - mn1);
            C[j][3] = __expf(C[j][3] - mn1);
            sum0 += C[j][0] + C[j][1];
            sum1 += C[j][2] + C[j][3];
        }
        sum0 += __shfl_xor_sync(0xffffffffu, sum0, 1);
        sum0 += __shfl_xor_sync(0xffffffffu, sum0, 2);
        sum1 += __shfl_xor_sync(0xffffffffu, sum1, 1);
        sum1 += __shfl_xor_sync(0xffffffffu, sum1, 2);
        l0 = l0 * corr0 + sum0;
        l1 = l1 * corr1 + sum1;

#pragma unroll
        for (int j = 0; j < 8; j++) {
            O[j][0] *= corr0; O[j][1] *= corr0;
            O[j][2] *= corr1; O[j][3] *= corr1;
        }

#pragma unroll
        for (int u = 0; u < 4; u++) {
            uint32_t ph[4], pl[4];
#pragma unroll
            for (int half = 0; half < 2; half++) {
                const float* cc = C[2 * u + half];
                uint32_t h0 = packbf(cc[0], cc[1]);
                uint32_t h1 = packbf(cc[2], cc[3]);
                float r00 = cc[0] - __uint_as_float(h0 << 16);
                float r01 = cc[1] - __uint_as_float(h0 & 0xFFFF0000u);
                float r10 = cc[2] - __uint_as_float(h1 << 16);
                float r11 = cc[3] - __uint_as_float(h1 & 0xFFFF0000u);
                ph[2 * half]     = h0;
                ph[2 * half + 1] = h1;
                pl[2 * half]     = packbf(r00, r01);
                pl[2 * half + 1] = packbf(r10, r11);
            }
#pragma unroll
            for (int jd = 0; jd < 8; jd++) {
                uint32_t vb[4];
                ldsm4t(vb, vb_base + u * (16 * RSB) + jd * 16);
                mma16816(O[jd], ph, vb[0], vb[1]);
                mma16816(O[jd], pl, vb[0], vb[1]);
                mma16816(O[jd], ph, vb[2], vb[3]);
            }
        }
        __syncthreads();
    }

    const float inv0 = 1.f / l0;
    const float inv1 = 1.f / l1;
    const int srow0 = s0 + wid * 16 + qid;
    const int srow1 = srow0 + 8;
#pragma unroll
    for (int jd = 0; jd < 8; jd++) {
        int d = 8 * jd + 2 * l2;
        float* p0 = out + (((size_t)(b * S_ + srow0)) * H_ + h) * DH + d;
        float* p1 = out + (((size_t)(b * S_ + srow1)) * H_ + h) * DH + d;
        *(float2*)p0 = make_float2(O[jd][0] * inv0, O[jd][1] * inv0);
        *(float2*)p1 = make_float2(O[jd][2] * inv1, O[jd][3] * inv1);
    }
}

// ---------------------------------------------------------------------------
extern "C" void kernel_launch(void* const* d_in, const int* in_sizes, int n_in,
                              void* d_out, int out_size)
{
    const float* x  = (const float*)d_in[0];
    const float* Wq = (const float*)d_in[1];
    const float* bq = (const float*)d_in[2];
    const float* Wv = (const float*)d_in[3];
    const float* bv = (const float*)d_in[4];
    const float* hp = (const float*)d_in[5];
    float* out = (float*)d_out;

    split_kernel<<<6144, 256>>>(x, Wq, Wv);
    whp_kernel<<<dim3(4, 96), 256>>>(Wq, bq, hp);

    const size_t bsmem = (size_t)(BK_B * 68 + BK_B * 96) * sizeof(float);
    cudaFuncSetAttribute(bucket_kernel,
                         cudaFuncAttributeMaxDynamicSharedMemorySize, (int)bsmem);
    bucket_kernel<<<64, 256, bsmem>>>(x);

    proj_tc_kernel<<<dim3(8, 32, 2), 256>>>(bq, bv);

    attn_kernel<<<dim3(S_ / 64, B_ * H_), 128>>>(out);
}

// round 5
// speedup vs baseline: 4.2124x; 1.0022x over previous
#include <cuda_runtime.h>
#include <cuda_bf16.h>
#include <math.h>
#include <stdint.h>

#define B_ 2
#define S_ 2048
#define E_ 1024
#define H_ 16
#define DH 64

// Scratch (device globals — no allocation allowed)
__device__ __nv_bfloat16 g_xh[(size_t)B_ * S_ * E_];
__device__ __nv_bfloat16 g_xl[(size_t)B_ * S_ * E_];
__device__ __nv_bfloat16 g_Wqh[(size_t)E_ * E_];
__device__ __nv_bfloat16 g_Wql[(size_t)E_ * E_];
__device__ __nv_bfloat16 g_Wvh[(size_t)E_ * E_];
__device__ __nv_bfloat16 g_Wvl[(size_t)E_ * E_];
__device__ __nv_bfloat16 g_Qh[(size_t)B_ * H_ * S_ * DH];
__device__ __nv_bfloat16 g_Ql[(size_t)B_ * H_ * S_ * DH];
__device__ __nv_bfloat16 g_Vh[(size_t)B_ * H_ * S_ * DH];
__device__ __nv_bfloat16 g_Vl[(size_t)B_ * H_ * S_ * DH];
__device__ float g_Whp[(size_t)E_ * 96];     // [e][h*6+n]
__device__ float g_cbias[96];
__device__ int   g_bkt[B_ * H_ * S_];

typedef unsigned long long u64;
union F2 { u64 u; float2 f; };

__device__ __forceinline__ u64 dup2(float x) {
    u64 r; asm("mov.b64 %0,{%1,%1};" : "=l"(r) : "f"(x)); return r;
}
__device__ __forceinline__ void fma2(u64& d, u64 a, u64 b) {
    asm("fma.rn.f32x2 %0,%1,%2,%3;" : "=l"(d) : "l"(a), "l"(b), "l"(d));
}
__device__ __forceinline__ void ldsm4(uint32_t* r, uint32_t a) {
    asm volatile("ldmatrix.sync.aligned.m8n8.x4.shared.b16 {%0,%1,%2,%3},[%4];"
                 : "=r"(r[0]), "=r"(r[1]), "=r"(r[2]), "=r"(r[3]) : "r"(a));
}
__device__ __forceinline__ void ldsm4t(uint32_t* r, uint32_t a) {
    asm volatile("ldmatrix.sync.aligned.m8n8.x4.trans.shared.b16 {%0,%1,%2,%3},[%4];"
                 : "=r"(r[0]), "=r"(r[1]), "=r"(r[2]), "=r"(r[3]) : "r"(a));
}
__device__ __forceinline__ void mma16816(float* c, const uint32_t* a,
                                         uint32_t b0, uint32_t b1) {
    asm volatile(
        "mma.sync.aligned.m16n8k16.row.col.f32.bf16.bf16.f32 "
        "{%0,%1,%2,%3},{%4,%5,%6,%7},{%8,%9},{%0,%1,%2,%3};"
        : "+f"(c[0]), "+f"(c[1]), "+f"(c[2]), "+f"(c[3])
        : "r"(a[0]), "r"(a[1]), "r"(a[2]), "r"(a[3]), "r"(b0), "r"(b1));
}
__device__ __forceinline__ uint32_t packbf(float lo, float hi) {
    uint32_t r; asm("cvt.rn.bf16x2.f32 %0,%1,%2;" : "=r"(r) : "f"(hi), "f"(lo));
    return r;
}

// ---------------------------------------------------------------------------
// Split x, Wq, Wv into bf16 hi/lo pairs. 4 floats per thread.
// ---------------------------------------------------------------------------
__global__ __launch_bounds__(256)
void split_kernel(const float* __restrict__ x, const float* __restrict__ Wq,
                  const float* __restrict__ Wv)
{
    size_t idx4 = (size_t)blockIdx.x * 256 + threadIdx.x;
    size_t flat = idx4 * 4;
    const float* src; __nv_bfloat16* dh; __nv_bfloat16* dl; size_t off;
    const size_t NX = (size_t)B_ * S_ * E_;       // 4M
    const size_t NW = (size_t)E_ * E_;            // 1M
    if (flat < NX)            { src = x;  dh = g_xh;  dl = g_xl;  off = flat; }
    else if (flat < NX + NW)  { src = Wq; dh = g_Wqh; dl = g_Wql; off = flat - NX; }
    else                      { src = Wv; dh = g_Wvh; dl = g_Wvl; off = flat - NX - NW; }

    float4 v = *(const float4*)(src + off);
    float vv[4] = {v.x, v.y, v.z, v.w};
    __align__(8) __nv_bfloat16 hi[4], lo[4];
#pragma unroll
    for (int j = 0; j < 4; j++) {
        hi[j] = __float2bfloat16(vv[j]);
        lo[j] = __float2bfloat16(vv[j] - __bfloat162float(hi[j]));
    }
    *(uint2*)(dh + off) = *(const uint2*)hi;
    *(uint2*)(dl + off) = *(const uint2*)lo;
}

// ---------------------------------------------------------------------------
// Whp[e][h*6+n] = sum_d Wq[h*64+d][e] * hp[d][n]  ;  cbias[hn] too.
// grid (4, 96), 256 threads: tid -> e, blockIdx.y -> hn.
// ---------------------------------------------------------------------------
__global__ __launch_bounds__(256)
void whp_kernel(const float* __restrict__ Wq, const float* __restrict__ bq,
                const float* __restrict__ hp)
{
    const int hn = blockIdx.y;
    const int h = hn / 6, n = hn % 6;
    const int e = blockIdx.x * 256 + threadIdx.x;
    float acc = 0.f;
#pragma unroll 8
    for (int d = 0; d < 64; d++)
        acc = fmaf(Wq[(size_t)(h * 64 + d) * E_ + e], __ldg(hp + d * 6 + n), acc);
    g_Whp[(size_t)e * 96 + hn] = acc;
    if (blockIdx.x == 0 && threadIdx.x == 0) {
        float cb = hp[64 * 6 + n];
        for (int d = 0; d < 64; d++)
            cb = fmaf(bq[h * 64 + d], hp[d * 6 + n], cb);
        g_cbias[hn] = cb;
    }
}

// ---------------------------------------------------------------------------
// Bucket GEMM: proj[m][hn] = sum_e x[m][e]*Whp[e][hn] + cbias[hn]; sign bits.
// grid 64 (64 rows each), 256 threads, f32x2. smem: sx[128k][68] + sw[128k][96].
// ---------------------------------------------------------------------------
#define BK_B 128
__global__ __launch_bounds__(256)
void bucket_kernel(const float* __restrict__ x)
{
    extern __shared__ float bsm[];
    float* sx = bsm;                 // [BK_B][68]  (transposed x chunk)
    float* sw = bsm + BK_B * 68;     // [BK_B][96]

    const int tid = threadIdx.x;
    const int tx = tid & 31;         // cols tx, tx+32, tx+64
    const int ty = tid >> 5;         // rows 8*ty .. 8*ty+7
    const int m0 = blockIdx.x * 64;

    u64 acc[4][3];
#pragma unroll
    for (int p = 0; p < 4; p++)
#pragma unroll
        for (int c = 0; c < 3; c++) acc[p][c] = dup2(g_cbias[tx + 32 * c]);

    for (int k0 = 0; k0 < E_; k0 += BK_B) {
        // stage x transposed: rows m0..m0+63, cols k0..k0+127
#pragma unroll
        for (int it = 0; it < 8; it++) {
            int idx = it * 256 + tid;          // 0..2047
            int r = idx >> 5;
            int c4 = (idx & 31) << 2;
            float4 v = *(const float4*)(x + (size_t)(m0 + r) * E_ + k0 + c4);
            sx[(c4 + 0) * 68 + r] = v.x; sx[(c4 + 1) * 68 + r] = v.y;
            sx[(c4 + 2) * 68 + r] = v.z; sx[(c4 + 3) * 68 + r] = v.w;
        }
        // stage Whp chunk: linear copy [128][96]
#pragma unroll
        for (int it = 0; it < 12; it++) {
            int u4 = it * 256 + tid;           // 0..3071 uint4
            *(uint4*)(sw + u4 * 4) =
                *(const uint4*)(g_Whp + (size_t)k0 * 96 + u4 * 4);
        }
        __syncthreads();

#pragma unroll 4
        for (int k = 0; k < BK_B; k++) {
            ulonglong2 x01 = *(const ulonglong2*)(sx + k * 68 + 8 * ty);
            ulonglong2 x23 = *(const ulonglong2*)(sx + k * 68 + 8 * ty + 4);
            u64 xp[4] = {x01.x, x01.y, x23.x, x23.y};
            u64 w0 = dup2(sw[k * 96 + tx]);
            u64 w1 = dup2(sw[k * 96 + tx + 32]);
            u64 w2 = dup2(sw[k * 96 + tx + 64]);
#pragma unroll
            for (int p = 0; p < 4; p++) {
                fma2(acc[p][0], xp[p], w0);
                fma2(acc[p][1], xp[p], w1);
                fma2(acc[p][2], xp[p], w2);
            }
        }
        __syncthreads();
    }

    // write proj to smem (reuse sx region), then assemble buckets
    float* sproj = sx;               // [64][96]
#pragma unroll
    for (int p = 0; p < 4; p++) {
#pragma unroll
        for (int c = 0; c < 3; c++) {
            F2 u; u.u = acc[p][c];
            sproj[(8 * ty + 2 * p) * 96 + tx + 32 * c]     = u.f.x;
            sproj[(8 * ty + 2 * p + 1) * 96 + tx + 32 * c] = u.f.y;
        }
    }
    __syncthreads();

#pragma unroll
    for (int u = 0; u < 4; u++) {
        int o = u * 256 + tid;       // 0..1023 = 64 rows x 16 heads
        int row = o >> 4, h = o & 15;
        int bucket = 0;
#pragma unroll
        for (int n = 0; n < 6; n++)
            if (sproj[row * 96 + h * 6 + n] >= 0.f) bucket |= (1 << n);
        int m = m0 + row;
        int b = m >> 11, s = m & (S_ - 1);
        g_bkt[(b * H_ + h) * S_ + s] = bucket;
    }
}

// ---------------------------------------------------------------------------
// Tensor-core projection GEMM (bf16 x3): C = x @ W^T + bias -> hi/lo splits.
// CTA 128x128, BK=32, 8 warps (4m x 2n), warp tile 32x64.
// grid (8, 32, 2): z=0 -> Q, z=1 -> V.
// ---------------------------------------------------------------------------
#define PST 40   // smem row stride (bf16 elems), 80 bytes
__global__ __launch_bounds__(256, 2)
void proj_tc_kernel(const float* __restrict__ bq, const float* __restrict__ bv)
{
    __shared__ __align__(16) __nv_bfloat16 sAh[128 * PST];
    __shared__ __align__(16) __nv_bfloat16 sAl[128 * PST];
    __shared__ __align__(16) __nv_bfloat16 sBh[128 * PST];
    __shared__ __align__(16) __nv_bfloat16 sBl[128 * PST];

    const int z = blockIdx.z;
    const __nv_bfloat16* Bh_g = z ? g_Wvh : g_Wqh;
    const __nv_bfloat16* Bl_g = z ? g_Wvl : g_Wql;
    const float* bias = z ? bv : bq;
    __nv_bfloat16* Hh = z ? g_Vh : g_Qh;
    __nv_bfloat16* Hl = z ? g_Vl : g_Ql;

    const int tid = threadIdx.x;
    const int wid = tid >> 5, lane = tid & 31;
    const int qid = lane >> 2, l2 = lane & 3;
    const int sel = lane >> 3, l7 = lane & 7;
    const int wm = wid & 3, wn = wid >> 2;
    const int m0 = blockIdx.y << 7;
    const int n0 = blockIdx.x << 7;

    const uint32_t aAh = (uint32_t)__cvta_generic_to_shared(sAh);
    const uint32_t aAl = (uint32_t)__cvta_generic_to_shared(sAl);
    const uint32_t aBh = (uint32_t)__cvta_generic_to_shared(sBh);
    const uint32_t aBl = (uint32_t)__cvta_generic_to_shared(sBl);

    float C[2][8][4];
#pragma unroll
    for (int a = 0; a < 2; a++)
#pragma unroll
        for (int j = 0; j < 8; j++)
#pragma unroll
            for (int t = 0; t < 4; t++) C[a][j][t] = 0.f;

    const uint32_t aoff = (uint32_t)((wm * 32 + (sel & 1) * 8 + l7) * (PST * 2)
                                     + (sel >> 1) * 16);
    const uint32_t bbase = ((sel < 2) ? aBh : aBl)
                         + (wn * 64 + l7) * (PST * 2) + (sel & 1) * 16;

    for (int k0 = 0; k0 < E_; k0 += 32) {
#pragma unroll
        for (int p = 0; p < 2; p++) {
            int idx = tid * 2 + p;          // 0..511
            int r = idx >> 2;
            int cu = (idx & 3) << 3;        // bf16 col offset
            size_t gx = (size_t)(m0 + r) * E_ + k0 + cu;
            size_t gw = (size_t)(n0 + r) * E_ + k0 + cu;
            *(uint4*)(sAh + r * PST + cu) = *(const uint4*)(g_xh + gx);
            *(uint4*)(sAl + r * PST + cu) = *(const uint4*)(g_xl + gx);
            *(uint4*)(sBh + r * PST + cu) = *(const uint4*)(Bh_g + gw);
            *(uint4*)(sBl + r * PST + cu) = *(const uint4*)(Bl_g + gw);
        }
        __syncthreads();

#pragma unroll
        for (int kk = 0; kk < 2; kk++) {
            uint32_t Ahf[2][4], Alf[2][4];
#pragma unroll
            for (int a = 0; a < 2; a++) {
                uint32_t ra = aoff + a * 16 * (PST * 2) + kk * 32;
                ldsm4(Ahf[a], aAh + ra);
                ldsm4(Alf[a], aAl + ra);
            }
#pragma unroll
            for (int j = 0; j < 8; j++) {
                uint32_t bb[4];
                ldsm4(bb, bbase + j * 8 * (PST * 2) + kk * 32);
#pragma unroll
                for (int a = 0; a < 2; a++) {
                    mma16816(C[a][j], Ahf[a], bb[0], bb[1]);
                    mma16816(C[a][j], Alf[a], bb[0], bb[1]);
                    mma16816(C[a][j], Ahf[a], bb[2], bb[3]);
                }
            }
        }
        __syncthreads();
    }

    // epilogue: + bias (fp32), split hi/lo, scatter to [B,H,S,Dh]
#pragma unroll
    for (int a = 0; a < 2; a++) {
        int mrow = m0 + wm * 32 + a * 16 + qid;
#pragma unroll
        for (int j = 0; j < 8; j++) {
            int n = n0 + wn * 64 + j * 8 + 2 * l2;
            int h = n >> 6, d = n & 63;
            float b0 = bias[n], b1 = bias[n + 1];
#pragma unroll
            for (int half = 0; half < 2; half++) {
                int m = mrow + half * 8;
                int b = m >> 11, s = m & (S_ - 1);
                size_t off = (((size_t)(b * H_ + h)) * S_ + s) * DH + d;
                float v0 = C[a][j][2 * half + 0] + b0;
                float v1 = C[a][j][2 * half + 1] + b1;
                uint32_t hi = packbf(v0, v1);
                float l0 = v0 - __uint_as_float(hi << 16);
                float l1 = v1 - __uint_as_float(hi & 0xFFFF0000u);
                *(uint32_t*)(Hh + off) = hi;
                *(uint32_t*)(Hl + off) = packbf(l0, l1);
            }
        }
    }
}

// ---------------------------------------------------------------------------
// Tensor-core flash attention (unchanged from R3).
// ---------------------------------------------------------------------------
#define RS 72
#define RSB 144

__global__ __launch_bounds__(128, 3)
void attn_kernel(float* __restrict__ out)
{
    __shared__ __align__(16) __nv_bfloat16 sKh[64 * RS];
    __shared__ __align__(16) __nv_bfloat16 sKl[64 * RS];
    __shared__ __align__(16) __nv_bfloat16 sVh[64 * RS];
    __shared__ __align__(16) __nv_bfloat16 sVl[64 * RS];
    __shared__ int bksm[64];

    const int tid = threadIdx.x;
    const int wid = tid >> 5, lane = tid & 31;
    const int qid = lane >> 2;
    const int l2  = lane & 3;
    const int sel = lane >> 3, l7 = lane & 7;

    const int bh = blockIdx.y;
    const int b = bh >> 4, h = bh & 15;
    const int s0 = blockIdx.x << 6;
    const __nv_bfloat16* Qh_g = g_Qh + (size_t)bh * S_ * DH;
    const __nv_bfloat16* Ql_g = g_Ql + (size_t)bh * S_ * DH;
    const __nv_bfloat16* Vh_g = g_Vh + (size_t)bh * S_ * DH;
    const __nv_bfloat16* Vl_g = g_Vl + (size_t)bh * S_ * DH;
    const int* bkp = g_bkt + bh * S_;

    const uint32_t aKh = (uint32_t)__cvta_generic_to_shared(sKh);
    const uint32_t aKl = (uint32_t)__cvta_generic_to_shared(sKl);
    const uint32_t aVh = (uint32_t)__cvta_generic_to_shared(sVh);
    const uint32_t aVl = (uint32_t)__cvta_generic_to_shared(sVl);

#pragma unroll
    for (int i = tid; i < 512; i += 128) {
        int r = i >> 3, c = (i & 7) << 3;
        *(uint4*)(sKh + r * RS + c) = *(const uint4*)(Qh_g + (size_t)(s0 + r) * DH + c);
        *(uint4*)(sKl + r * RS + c) = *(const uint4*)(Ql_g + (size_t)(s0 + r) * DH + c);
    }
    __syncthreads();

    uint32_t Ah[4][4], Al[4][4];
    {
        uint32_t qoff = (uint32_t)((wid * 16 + (sel & 1) * 8 + l7) * RSB + (sel >> 1) * 16);
#pragma unroll
        for (int u = 0; u < 4; u++) {
            ldsm4(Ah[u], aKh + qoff + u * 32);
            ldsm4(Al[u], aKl + qoff + u * 32);
        }
    }
    const int bq0 = bkp[s0 + wid * 16 + qid];
    const int bq1 = bkp[s0 + wid * 16 + qid + 8];
    __syncthreads();

    float O[8][4];
#pragma unroll
    for (int j = 0; j < 8; j++)
#pragma unroll
        for (int k = 0; k < 4; k++) O[j][k] = 0.f;
    float m0 = -INFINITY, m1 = -INFINITY, l0 = 0.f, l1 = 0.f;

    const uint32_t kb_base = ((sel < 2) ? aKh : aKl) + l7 * RSB + (sel & 1) * 16;
    const uint32_t vb_base = ((sel < 2) ? aVh : aVl) + (l7 + (sel & 1) * 8) * RSB;

    for (int t0 = 0; t0 < S_; t0 += 64) {
#pragma unroll
        for (int i = tid; i < 512; i += 128) {
            int r = i >> 3, c = (i & 7) << 3;
            size_t go = (size_t)(t0 + r) * DH + c;
            *(uint4*)(sKh + r * RS + c) = *(const uint4*)(Qh_g + go);
            *(uint4*)(sKl + r * RS + c) = *(const uint4*)(Ql_g + go);
            *(uint4*)(sVh + r * RS + c) = *(const uint4*)(Vh_g + go);
            *(uint4*)(sVl + r * RS + c) = *(const uint4*)(Vl_g + go);
        }
        if (tid < 64) bksm[tid] = bkp[t0 + tid];
        __syncthreads();

        float C[8][4];
#pragma unroll
        for (int j = 0; j < 8; j++)
#pragma unroll
            for (int k = 0; k < 4; k++) C[j][k] = 0.f;

#pragma unroll
        for (int j = 0; j < 8; j++) {
#pragma unroll
            for (int u = 0; u < 4; u++) {
                uint32_t kb[4];
                ldsm4(kb, kb_base + j * (8 * RSB) + u * 32);
                mma16816(C[j], Ah[u], kb[0], kb[1]);
                mma16816(C[j], Al[u], kb[0], kb[1]);
                mma16816(C[j], Ah[u], kb[2], kb[3]);
            }
        }

        float rmax0 = -INFINITY, rmax1 = -INFINITY;
#pragma unroll
        for (int j = 0; j < 8; j++) {
            int tcol = 8 * j + 2 * l2;
            int bk0 = bksm[tcol], bk1 = bksm[tcol + 1];
            float cf00 = (bq0 == bk0) ? 1.96875f : 1.9375f;
            float cf01 = (bq0 == bk1) ? 1.96875f : 1.9375f;
            float cf10 = (bq1 == bk0) ? 1.96875f : 1.9375f;
            float cf11 = (bq1 == bk1) ? 1.96875f : 1.9375f;
            C[j][0] *= cf00; C[j][1] *= cf01;
            C[j][2] *= cf10; C[j][3] *= cf11;
            rmax0 = fmaxf(rmax0, fmaxf(C[j][0], C[j][1]));
            rmax1 = fmaxf(rmax1, fmaxf(C[j][2], C[j][3]));
        }
        rmax0 = fmaxf(rmax0, __shfl_xor_sync(0xffffffffu, rmax0, 1));
        rmax0 = fmaxf(rmax0, __shfl_xor_sync(0xffffffffu, rmax0, 2));
        rmax1 = fmaxf(rmax1, __shfl_xor_sync(0xffffffffu, rmax1, 1));
        rmax1 = fmaxf(rmax1, __shfl_xor_sync(0xffffffffu, rmax1, 2));

        float mn0 = fmaxf(m0, rmax0);
        float mn1 = fmaxf(m1, rmax1);
        float corr0 = __expf(m0 - mn0);
        float corr1 = __expf(m1 - mn1);
        m0 = mn0; m1 = mn1;

        float sum0 = 0.f, sum1 = 0.f;
#pragma unroll
        for (int j = 0; j < 8; j++) {
            C[j][0] = __expf(C[j][0] - mn0);
            C[j][1] = __expf(C[j][1] - mn0);
            C[j][2] = __expf(C[j][2] - mn1);
            C[j][3] = __expf(C[j][3] - mn1);
            sum0 += C[j][0] + C[j][1];
            sum1 += C[j][2] + C[j][3];
        }
        sum0 += __shfl_xor_sync(0xffffffffu, sum0, 1);
        sum0 += __shfl_xor_sync(0xffffffffu, sum0, 2);
        sum1 += __shfl_xor_sync(0xffffffffu, sum1, 1);
        sum1 += __shfl_xor_sync(0xffffffffu, sum1, 2);
        l0 = l0 * corr0 + sum0;
        l1 = l1 * corr1 + sum1;

#pragma unroll
        for (int j = 0; j < 8; j++) {
            O[j][0] *= corr0; O[j][1] *= corr0;
            O[j][2] *= corr1; O[j][3] *= corr1;
        }

#pragma unroll
        for (int u = 0; u < 4; u++) {
            uint32_t ph[4], pl[4];
#pragma unroll
            for (int half = 0; half < 2; half++) {
                const float* cc = C[2 * u + half];
                uint32_t h0 = packbf(cc[0], cc[1]);
                uint32_t h1 = packbf(cc[2], cc[3]);
                float r00 = cc[0] - __uint_as_float(h0 << 16);
                float r01 = cc[1] - __uint_as_float(h0 & 0xFFFF0000u);
                float r10 = cc[2] - __uint_as_float(h1 << 16);
                float r11 = cc[3] - __uint_as_float(h1 & 0xFFFF0000u);
                ph[2 * half]     = h0;
                ph[2 * half + 1] = h1;
                pl[2 * half]     = packbf(r00, r01);
                pl[2 * half + 1] = packbf(r10, r11);
            }
#pragma unroll
            for (int jd = 0; jd < 8; jd++) {
                uint32_t vb[4];
                ldsm4t(vb, vb_base + u * (16 * RSB) + jd * 16);
                mma16816(O[jd], ph, vb[0], vb[1]);
                mma16816(O[jd], pl, vb[0], vb[1]);
                mma16816(O[jd], ph, vb[2], vb[3]);
            }
        }
        __syncthreads();
    }

    const float inv0 = 1.f / l0;
    const float inv1 = 1.f / l1;
    const int srow0 = s0 + wid * 16 + qid;
    const int srow1 = srow0 + 8;
#pragma unroll
    for (int jd = 0; jd < 8; jd++) {
        int d = 8 * jd + 2 * l2;
        float* p0 = out + (((size_t)(b * S_ + srow0)) * H_ + h) * DH + d;
        float* p1 = out + (((size_t)(b * S_ + srow1)) * H_ + h) * DH + d;
        *(float2*)p0 = make_float2(O[jd][0] * inv0, O[jd][1] * inv0);
        *(float2*)p1 = make_float2(O[jd][2] * inv1, O[jd][3] * inv1);
    }
}

// ---------------------------------------------------------------------------
extern "C" void kernel_launch(void* const* d_in, const int* in_sizes, int n_in,
                              void* d_out, int out_size)
{
    const float* x  = (const float*)d_in[0];
    const float* Wq = (const float*)d_in[1];
    const float* bq = (const float*)d_in[2];
    const float* Wv = (const float*)d_in[3];
    const float* bv = (const float*)d_in[4];
    const float* hp = (const float*)d_in[5];
    float* out = (float*)d_out;

    split_kernel<<<6144, 256>>>(x, Wq, Wv);
    whp_kernel<<<dim3(4, 96), 256>>>(Wq, bq, hp);

    const size_t bsmem = (size_t)(BK_B * 68 + BK_B * 96) * sizeof(float);
    cudaFuncSetAttribute(bucket_kernel,
                         cudaFuncAttributeMaxDynamicSharedMemorySize, (int)bsmem);
    bucket_kernel<<<64, 256, bsmem>>>(x);

    proj_tc_kernel<<<dim3(8, 32, 2), 256>>>(bq, bv);

    attn_kernel<<<dim3(S_ / 64, B_ * H_), 128>>>(out);
}

// round 6
// speedup vs baseline: 4.4373x; 1.0534x over previous
#include <cuda_runtime.h>
#include <cuda_bf16.h>
#include <math.h>
#include <stdint.h>

#define B_ 2
#define S_ 2048
#define E_ 1024
#define H_ 16
#define DH 64

// Scratch (device globals — no allocation allowed)
__device__ __nv_bfloat16 g_xh[(size_t)B_ * S_ * E_];
__device__ __nv_bfloat16 g_xl[(size_t)B_ * S_ * E_];
__device__ __nv_bfloat16 g_Wqh[(size_t)E_ * E_];
__device__ __nv_bfloat16 g_Wql[(size_t)E_ * E_];
__device__ __nv_bfloat16 g_Wvh[(size_t)E_ * E_];
__device__ __nv_bfloat16 g_Wvl[(size_t)E_ * E_];
__device__ __nv_bfloat16 g_Qh[(size_t)B_ * H_ * S_ * DH];
__device__ __nv_bfloat16 g_Ql[(size_t)B_ * H_ * S_ * DH];
__device__ __nv_bfloat16 g_Vh[(size_t)B_ * H_ * S_ * DH];
__device__ __nv_bfloat16 g_Vl[(size_t)B_ * H_ * S_ * DH];
__device__ float g_Whp[(size_t)E_ * 96];     // [e][h*6+n]
__device__ float g_cbias[96];
__device__ int   g_bkt[B_ * H_ * S_];

typedef unsigned long long u64;
union F2 { u64 u; float2 f; };

__device__ __forceinline__ u64 dup2(float x) {
    u64 r; asm("mov.b64 %0,{%1,%1};" : "=l"(r) : "f"(x)); return r;
}
__device__ __forceinline__ void fma2(u64& d, u64 a, u64 b) {
    asm("fma.rn.f32x2 %0,%1,%2,%3;" : "=l"(d) : "l"(a), "l"(b), "l"(d));
}
__device__ __forceinline__ void ldsm4(uint32_t* r, uint32_t a) {
    asm volatile("ldmatrix.sync.aligned.m8n8.x4.shared.b16 {%0,%1,%2,%3},[%4];"
                 : "=r"(r[0]), "=r"(r[1]), "=r"(r[2]), "=r"(r[3]) : "r"(a));
}
__device__ __forceinline__ void ldsm4t(uint32_t* r, uint32_t a) {
    asm volatile("ldmatrix.sync.aligned.m8n8.x4.trans.shared.b16 {%0,%1,%2,%3},[%4];"
                 : "=r"(r[0]), "=r"(r[1]), "=r"(r[2]), "=r"(r[3]) : "r"(a));
}
__device__ __forceinline__ void mma16816(float* c, const uint32_t* a,
                                         uint32_t b0, uint32_t b1) {
    asm volatile(
        "mma.sync.aligned.m16n8k16.row.col.f32.bf16.bf16.f32 "
        "{%0,%1,%2,%3},{%4,%5,%6,%7},{%8,%9},{%0,%1,%2,%3};"
        : "+f"(c[0]), "+f"(c[1]), "+f"(c[2]), "+f"(c[3])
        : "r"(a[0]), "r"(a[1]), "r"(a[2]), "r"(a[3]), "r"(b0), "r"(b1));
}
__device__ __forceinline__ uint32_t packbf(float lo, float hi) {
    uint32_t r; asm("cvt.rn.bf16x2.f32 %0,%1,%2;" : "=r"(r) : "f"(hi), "f"(lo));
    return r;
}
__device__ __forceinline__ void cpa16(uint32_t dst, const void* src) {
    asm volatile("cp.async.cg.shared.global [%0],[%1],16;" :: "r"(dst), "l"(src));
}
__device__ __forceinline__ void cpa4(uint32_t dst, const void* src) {
    asm volatile("cp.async.ca.shared.global [%0],[%1],4;" :: "r"(dst), "l"(src));
}
#define CP_COMMIT() asm volatile("cp.async.commit_group;")
template <int N>
__device__ __forceinline__ void cp_wait() {
    asm volatile("cp.async.wait_group %0;" :: "n"(N));
}

// ---------------------------------------------------------------------------
// Split x, Wq, Wv into bf16 hi/lo pairs. 4 floats per thread.
// ---------------------------------------------------------------------------
__global__ __launch_bounds__(256)
void split_kernel(const float* __restrict__ x, const float* __restrict__ Wq,
                  const float* __restrict__ Wv)
{
    size_t idx4 = (size_t)blockIdx.x * 256 + threadIdx.x;
    size_t flat = idx4 * 4;
    const float* src; __nv_bfloat16* dh; __nv_bfloat16* dl; size_t off;
    const size_t NX = (size_t)B_ * S_ * E_;
    const size_t NW = (size_t)E_ * E_;
    if (flat < NX)            { src = x;  dh = g_xh;  dl = g_xl;  off = flat; }
    else if (flat < NX + NW)  { src = Wq; dh = g_Wqh; dl = g_Wql; off = flat - NX; }
    else                      { src = Wv; dh = g_Wvh; dl = g_Wvl; off = flat - NX - NW; }

    float4 v = *(const float4*)(src + off);
    float vv[4] = {v.x, v.y, v.z, v.w};
    __align__(8) __nv_bfloat16 hi[4], lo[4];
#pragma unroll
    for (int j = 0; j < 4; j++) {
        hi[j] = __float2bfloat16(vv[j]);
        lo[j] = __float2bfloat16(vv[j] - __bfloat162float(hi[j]));
    }
    *(uint2*)(dh + off) = *(const uint2*)hi;
    *(uint2*)(dl + off) = *(const uint2*)lo;
}

// ---------------------------------------------------------------------------
// Whp[e][h*6+n] = sum_d Wq[h*64+d][e] * hp[d][n]  ;  cbias[hn] too.
// ---------------------------------------------------------------------------
__global__ __launch_bounds__(256)
void whp_kernel(const float* __restrict__ Wq, const float* __restrict__ bq,
                const float* __restrict__ hp)
{
    const int hn = blockIdx.y;
    const int h = hn / 6, n = hn % 6;
    const int e = blockIdx.x * 256 + threadIdx.x;
    float acc = 0.f;
#pragma unroll 8
    for (int d = 0; d < 64; d++)
        acc = fmaf(Wq[(size_t)(h * 64 + d) * E_ + e], __ldg(hp + d * 6 + n), acc);
    g_Whp[(size_t)e * 96 + hn] = acc;
    if (blockIdx.x == 0 && threadIdx.x == 0) {
        float cb = hp[64 * 6 + n];
        for (int d = 0; d < 64; d++)
            cb = fmaf(bq[h * 64 + d], hp[d * 6 + n], cb);
        g_cbias[hn] = cb;
    }
}

// ---------------------------------------------------------------------------
// Bucket GEMM (fp32 f32x2): proj[m][hn] = x @ Whp + cbias; sign bits.
// ---------------------------------------------------------------------------
#define BK_B 128
__global__ __launch_bounds__(256)
void bucket_kernel(const float* __restrict__ x)
{
    extern __shared__ float bsm[];
    float* sx = bsm;                 // [BK_B][68]
    float* sw = bsm + BK_B * 68;     // [BK_B][96]

    const int tid = threadIdx.x;
    const int tx = tid & 31;
    const int ty = tid >> 5;
    const int m0 = blockIdx.x * 64;

    u64 acc[4][3];
#pragma unroll
    for (int p = 0; p < 4; p++)
#pragma unroll
        for (int c = 0; c < 3; c++) acc[p][c] = dup2(g_cbias[tx + 32 * c]);

    for (int k0 = 0; k0 < E_; k0 += BK_B) {
#pragma unroll
        for (int it = 0; it < 8; it++) {
            int idx = it * 256 + tid;
            int r = idx >> 5;
            int c4 = (idx & 31) << 2;
            float4 v = *(const float4*)(x + (size_t)(m0 + r) * E_ + k0 + c4);
            sx[(c4 + 0) * 68 + r] = v.x; sx[(c4 + 1) * 68 + r] = v.y;
            sx[(c4 + 2) * 68 + r] = v.z; sx[(c4 + 3) * 68 + r] = v.w;
        }
#pragma unroll
        for (int it = 0; it < 12; it++) {
            int u4 = it * 256 + tid;
            *(uint4*)(sw + u4 * 4) =
                *(const uint4*)(g_Whp + (size_t)k0 * 96 + u4 * 4);
        }
        __syncthreads();

#pragma unroll 4
        for (int k = 0; k < BK_B; k++) {
            ulonglong2 x01 = *(const ulonglong2*)(sx + k * 68 + 8 * ty);
            ulonglong2 x23 = *(const ulonglong2*)(sx + k * 68 + 8 * ty + 4);
            u64 xp[4] = {x01.x, x01.y, x23.x, x23.y};
            u64 w0 = dup2(sw[k * 96 + tx]);
            u64 w1 = dup2(sw[k * 96 + tx + 32]);
            u64 w2 = dup2(sw[k * 96 + tx + 64]);
#pragma unroll
            for (int p = 0; p < 4; p++) {
                fma2(acc[p][0], xp[p], w0);
                fma2(acc[p][1], xp[p], w1);
                fma2(acc[p][2], xp[p], w2);
            }
        }
        __syncthreads();
    }

    float* sproj = sx;
#pragma unroll
    for (int p = 0; p < 4; p++) {
#pragma unroll
        for (int c = 0; c < 3; c++) {
            F2 u; u.u = acc[p][c];
            sproj[(8 * ty + 2 * p) * 96 + tx + 32 * c]     = u.f.x;
            sproj[(8 * ty + 2 * p + 1) * 96 + tx + 32 * c] = u.f.y;
        }
    }
    __syncthreads();

#pragma unroll
    for (int u = 0; u < 4; u++) {
        int o = u * 256 + tid;
        int row = o >> 4, h = o & 15;
        int bucket = 0;
#pragma unroll
        for (int n = 0; n < 6; n++)
            if (sproj[row * 96 + h * 6 + n] >= 0.f) bucket |= (1 << n);
        int m = m0 + row;
        int b = m >> 11, s = m & (S_ - 1);
        g_bkt[(b * H_ + h) * S_ + s] = bucket;
    }
}

// ---------------------------------------------------------------------------
// Tensor-core projection GEMM (bf16 x3) with 2-stage cp.async pipeline.
// CTA 128x128, BK=32, 8 warps (4m x 2n). grid (8, 32, 2).
// Dynamic smem per stage: Ah|Al|Bh|Bl each 128*PST bf16.
// ---------------------------------------------------------------------------
#define PST 40
#define PJ_TILE_B (128 * PST * 2)          // 10240 B per array
#define PJ_STAGE_B (4 * PJ_TILE_B)         // 40960 B per stage

__global__ __launch_bounds__(256, 2)
void proj_tc_kernel(const float* __restrict__ bq, const float* __restrict__ bv)
{
    extern __shared__ char psm[];
    const uint32_t aS = (uint32_t)__cvta_generic_to_shared(psm);

    const int z = blockIdx.z;
    const __nv_bfloat16* Bh_g = z ? g_Wvh : g_Wqh;
    const __nv_bfloat16* Bl_g = z ? g_Wvl : g_Wql;
    const float* bias = z ? bv : bq;
    __nv_bfloat16* Hh = z ? g_Vh : g_Qh;
    __nv_bfloat16* Hl = z ? g_Vl : g_Ql;

    const int tid = threadIdx.x;
    const int wid = tid >> 5, lane = tid & 31;
    const int qid = lane >> 2, l2 = lane & 3;
    const int sel = lane >> 3, l7 = lane & 7;
    const int wm = wid & 3, wn = wid >> 2;
    const int m0 = blockIdx.y << 7;
    const int n0 = blockIdx.x << 7;

    // per-thread load coords (2 uint4-rows per thread per array)
    const int r_ld[2]  = { (tid * 2) >> 2, (tid * 2 + 1) >> 2 };
    const int cu_ld[2] = { ((tid * 2) & 3) << 3, ((tid * 2 + 1) & 3) << 3 };

    float C[2][8][4];
#pragma unroll
    for (int a = 0; a < 2; a++)
#pragma unroll
        for (int j = 0; j < 8; j++)
#pragma unroll
            for (int t = 0; t < 4; t++) C[a][j][t] = 0.f;

    const uint32_t aoff = (uint32_t)((wm * 32 + (sel & 1) * 8 + l7) * (PST * 2)
                                     + (sel >> 1) * 16);
    const uint32_t bhl = (sel < 2) ? (2 * PJ_TILE_B) : (3 * PJ_TILE_B);
    const uint32_t boff = bhl + (wn * 64 + l7) * (PST * 2) + (sel & 1) * 16;

    // prefetch helper (macro-ish lambda)
    auto prefetch = [&](int st, int k0) {
#pragma unroll
        for (int p = 0; p < 2; p++) {
            int r = r_ld[p], cu = cu_ld[p];
            size_t gx = (size_t)(m0 + r) * E_ + k0 + cu;
            size_t gw = (size_t)(n0 + r) * E_ + k0 + cu;
            uint32_t so = aS + st * PJ_STAGE_B + (r * PST + cu) * 2;
            cpa16(so,                 g_xh + gx);
            cpa16(so + PJ_TILE_B,     g_xl + gx);
            cpa16(so + 2 * PJ_TILE_B, Bh_g + gw);
            cpa16(so + 3 * PJ_TILE_B, Bl_g + gw);
        }
    };

    prefetch(0, 0);
    CP_COMMIT();

    for (int kt = 0; kt < 32; kt++) {
        if (kt + 1 < 32) prefetch((kt + 1) & 1, (kt + 1) * 32);
        CP_COMMIT();
        cp_wait<1>();
        __syncthreads();

        const uint32_t stB = aS + (kt & 1) * PJ_STAGE_B;
#pragma unroll
        for (int kk = 0; kk < 2; kk++) {
            uint32_t Ahf[2][4], Alf[2][4];
#pragma unroll
            for (int a = 0; a < 2; a++) {
                uint32_t ra = stB + aoff + a * 16 * (PST * 2) + kk * 32;
                ldsm4(Ahf[a], ra);
                ldsm4(Alf[a], ra + PJ_TILE_B);
            }
#pragma unroll
            for (int j = 0; j < 8; j++) {
                uint32_t bb[4];
                ldsm4(bb, stB + boff + j * 8 * (PST * 2) + kk * 32);
#pragma unroll
                for (int a = 0; a < 2; a++) {
                    mma16816(C[a][j], Ahf[a], bb[0], bb[1]);
                    mma16816(C[a][j], Alf[a], bb[0], bb[1]);
                    mma16816(C[a][j], Ahf[a], bb[2], bb[3]);
                }
            }
        }
        __syncthreads();
    }

    // epilogue: + bias (fp32), split hi/lo, scatter to [B,H,S,Dh]
#pragma unroll
    for (int a = 0; a < 2; a++) {
        int mrow = m0 + wm * 32 + a * 16 + qid;
#pragma unroll
        for (int j = 0; j < 8; j++) {
            int n = n0 + wn * 64 + j * 8 + 2 * l2;
            int h = n >> 6, d = n & 63;
            float b0 = bias[n], b1 = bias[n + 1];
#pragma unroll
            for (int half = 0; half < 2; half++) {
                int m = mrow + half * 8;
                int b = m >> 11, s = m & (S_ - 1);
                size_t off = (((size_t)(b * H_ + h)) * S_ + s) * DH + d;
                float v0 = C[a][j][2 * half + 0] + b0;
                float v1 = C[a][j][2 * half + 1] + b1;
                uint32_t hi = packbf(v0, v1);
                float l0 = v0 - __uint_as_float(hi << 16);
                float l1 = v1 - __uint_as_float(hi & 0xFFFF0000u);
                *(uint32_t*)(Hh + off) = hi;
                *(uint32_t*)(Hl + off) = packbf(l0, l1);
            }
        }
    }
}

// ---------------------------------------------------------------------------
// Tensor-core flash attention, 2-stage cp.async pipeline for K/V tiles.
// CTA: 128 threads (4 warps), s-tile 64, t-tiles 64.
// Dynamic smem: 2 stages x [Kh|Kl|Vh|Vl] (64 x RS bf16 each) + bk[2][64].
// ---------------------------------------------------------------------------
#define RS 72
#define RSB 144
#define AT_TILE_B (64 * RS * 2)            // 9216 B
#define AT_STAGE_B (4 * AT_TILE_B)         // 36864 B
#define AT_BK_OFF (2 * AT_STAGE_B)         // 73728 B
#define AT_SMEM (AT_BK_OFF + 2 * 64 * 4)   // 74240 B

__global__ __launch_bounds__(128)
void attn_kernel(float* __restrict__ out)
{
    extern __shared__ char asm_[];
    const uint32_t aS = (uint32_t)__cvta_generic_to_shared(asm_);
    __nv_bfloat16* sK0h = (__nv_bfloat16*)asm_;                  // stage0 Kh (Q staging)
    int* bkArr = (int*)(asm_ + AT_BK_OFF);

    const int tid = threadIdx.x;
    const int wid = tid >> 5, lane = tid & 31;
    const int qid = lane >> 2;
    const int l2  = lane & 3;
    const int sel = lane >> 3, l7 = lane & 7;

    const int bh = blockIdx.y;
    const int b = bh >> 4, h = bh & 15;
    const int s0 = blockIdx.x << 6;
    const __nv_bfloat16* Qh_g = g_Qh + (size_t)bh * S_ * DH;
    const __nv_bfloat16* Ql_g = g_Ql + (size_t)bh * S_ * DH;
    const __nv_bfloat16* Vh_g = g_Vh + (size_t)bh * S_ * DH;
    const __nv_bfloat16* Vl_g = g_Vl + (size_t)bh * S_ * DH;
    const int* bkp = g_bkt + bh * S_;

    // ---- stage Q tile into stage-0 Kh/Kl region, extract A fragments ----
#pragma unroll
    for (int i = tid; i < 512; i += 128) {
        int r = i >> 3, c = (i & 7) << 3;
        *(uint4*)(sK0h + r * RS + c) =
            *(const uint4*)(Qh_g + (size_t)(s0 + r) * DH + c);
        *(uint4*)((__nv_bfloat16*)(asm_ + AT_TILE_B) + r * RS + c) =
            *(const uint4*)(Ql_g + (size_t)(s0 + r) * DH + c);
    }
    __syncthreads();

    uint32_t Ah[4][4], Al[4][4];
    {
        uint32_t qoff = aS + (uint32_t)((wid * 16 + (sel & 1) * 8 + l7) * RSB
                                        + (sel >> 1) * 16);
#pragma unroll
        for (int u = 0; u < 4; u++) {
            ldsm4(Ah[u], qoff + u * 32);
            ldsm4(Al[u], qoff + u * 32 + AT_TILE_B);
        }
    }
    const int bq0 = bkp[s0 + wid * 16 + qid];
    const int bq1 = bkp[s0 + wid * 16 + qid + 8];
    __syncthreads();   // done reading Q staging before prefetch overwrites

    float O[8][4];
#pragma unroll
    for (int j = 0; j < 8; j++)
#pragma unroll
        for (int k = 0; k < 4; k++) O[j][k] = 0.f;
    float m0 = -INFINITY, m1 = -INFINITY, l0 = 0.f, l1 = 0.f;

    const uint32_t khl = (sel < 2) ? 0u : (uint32_t)AT_TILE_B;
    const uint32_t kb_off = khl + l7 * RSB + (sel & 1) * 16;
    const uint32_t vhl = (sel < 2) ? (uint32_t)(2 * AT_TILE_B)
                                   : (uint32_t)(3 * AT_TILE_B);
    const uint32_t vb_off = vhl + (l7 + (sel & 1) * 8) * RSB;

    auto prefetch = [&](int st, int t0) {
#pragma unroll
        for (int i = tid; i < 512; i += 128) {
            int r = i >> 3, c = (i & 7) << 3;
            size_t go = (size_t)(t0 + r) * DH + c;
            uint32_t so = aS + st * AT_STAGE_B + (r * RS + c) * 2;
            cpa16(so,                 Qh_g + go);
            cpa16(so + AT_TILE_B,     Ql_g + go);
            cpa16(so + 2 * AT_TILE_B, Vh_g + go);
            cpa16(so + 3 * AT_TILE_B, Vl_g + go);
        }
        if (tid < 64)
            cpa4(aS + AT_BK_OFF + (st * 64 + tid) * 4, bkp + t0 + tid);
    };

    prefetch(0, 0);
    CP_COMMIT();

    for (int it = 0; it < S_ / 64; it++) {
        if (it + 1 < S_ / 64) prefetch((it + 1) & 1, (it + 1) * 64);
        CP_COMMIT();
        cp_wait<1>();
        __syncthreads();

        const int st = it & 1;
        const uint32_t stB = aS + st * AT_STAGE_B;
        const int* bks = bkArr + st * 64;

        // ---- S = Q K^T (x3 split) ----
        float C[8][4];
#pragma unroll
        for (int j = 0; j < 8; j++)
#pragma unroll
            for (int k = 0; k < 4; k++) C[j][k] = 0.f;

#pragma unroll
        for (int j = 0; j < 8; j++) {
#pragma unroll
            for (int u = 0; u < 4; u++) {
                uint32_t kb[4];
                ldsm4(kb, stB + kb_off + j * (8 * RSB) + u * 32);
                mma16816(C[j], Ah[u], kb[0], kb[1]);
                mma16816(C[j], Al[u], kb[0], kb[1]);
                mma16816(C[j], Ah[u], kb[2], kb[3]);
            }
        }

        // ---- coeff + online softmax ----
        float rmax0 = -INFINITY, rmax1 = -INFINITY;
#pragma unroll
        for (int j = 0; j < 8; j++) {
            int tcol = 8 * j + 2 * l2;
            int bk0 = bks[tcol], bk1 = bks[tcol + 1];
            float cf00 = (bq0 == bk0) ? 1.96875f : 1.9375f;
            float cf01 = (bq0 == bk1) ? 1.96875f : 1.9375f;
            float cf10 = (bq1 == bk0) ? 1.96875f : 1.9375f;
            float cf11 = (bq1 == bk1) ? 1.96875f : 1.9375f;
            C[j][0] *= cf00; C[j][1] *= cf01;
            C[j][2] *= cf10; C[j][3] *= cf11;
            rmax0 = fmaxf(rmax0, fmaxf(C[j][0], C[j][1]));
            rmax1 = fmaxf(rmax1, fmaxf(C[j][2], C[j][3]));
        }
        rmax0 = fmaxf(rmax0, __shfl_xor_sync(0xffffffffu, rmax0, 1));
        rmax0 = fmaxf(rmax0, __shfl_xor_sync(0xffffffffu, rmax0, 2));
        rmax1 = fmaxf(rmax1, __shfl_xor_sync(0xffffffffu, rmax1, 1));
        rmax1 = fmaxf(rmax1, __shfl_xor_sync(0xffffffffu, rmax1, 2));

        float mn0 = fmaxf(m0, rmax0);
        float mn1 = fmaxf(m1, rmax1);
        float corr0 = __expf(m0 - mn0);
        float corr1 = __expf(m1 - mn1);
        m0 = mn0; m1 = mn1;

        float sum0 = 0.f, sum1 = 0.f;
#pragma unroll
        for (int j = 0; j < 8; j++) {
            C[j][0] = __expf(C[j][0] - mn0);
            C[j][1] = __expf(C[j][1] - mn0);
            C[j][2] = __expf(C[j][2] - mn1);
            C[j][3] = __expf(C[j][3] - mn1);
            sum0 += C[j][0] + C[j][1];
            sum1 += C[j][2] + C[j][3];
        }
        sum0 += __shfl_xor_sync(0xffffffffu, sum0, 1);
        sum0 += __shfl_xor_sync(0xffffffffu, sum0, 2);
        sum1 += __shfl_xor_sync(0xffffffffu, sum1, 1);
        sum1 += __shfl_xor_sync(0xffffffffu, sum1, 2);
        l0 = l0 * corr0 + sum0;
        l1 = l1 * corr1 + sum1;

#pragma unroll
        for (int j = 0; j < 8; j++) {
            O[j][0] *= corr0; O[j][1] *= corr0;
            O[j][2] *= corr1; O[j][3] *= corr1;
        }

        // ---- O += P V (x3 split) ----
#pragma unroll
        for (int u = 0; u < 4; u++) {
            uint32_t ph[4], pl[4];
#pragma unroll
            for (int half = 0; half < 2; half++) {
                const float* cc = C[2 * u + half];
                uint32_t h0 = packbf(cc[0], cc[1]);
                uint32_t h1 = packbf(cc[2], cc[3]);
                float r00 = cc[0] - __uint_as_float(h0 << 16);
                float r01 = cc[1] - __uint_as_float(h0 & 0xFFFF0000u);
                float r10 = cc[2] - __uint_as_float(h1 << 16);
                float r11 = cc[3] - __uint_as_float(h1 & 0xFFFF0000u);
                ph[2 * half]     = h0;
                ph[2 * half + 1] = h1;
                pl[2 * half]     = packbf(r00, r01);
                pl[2 * half + 1] = packbf(r10, r11);
            }
#pragma unroll
            for (int jd = 0; jd < 8; jd++) {
                uint32_t vb[4];
                ldsm4t(vb, stB + vb_off + u * (16 * RSB) + jd * 16);
                mma16816(O[jd], ph, vb[0], vb[1]);
                mma16816(O[jd], pl, vb[0], vb[1]);
                mma16816(O[jd], ph, vb[2], vb[3]);
            }
        }
        __syncthreads();   // all warps done with this stage before overwrite
    }

    const float inv0 = 1.f / l0;
    const float inv1 = 1.f / l1;
    const int srow0 = s0 + wid * 16 + qid;
    const int srow1 = srow0 + 8;
#pragma unroll
    for (int jd = 0; jd < 8; jd++) {
        int d = 8 * jd + 2 * l2;
        float* p0 = out + (((size_t)(b * S_ + srow0)) * H_ + h) * DH + d;
        float* p1 = out + (((size_t)(b * S_ + srow1)) * H_ + h) * DH + d;
        *(float2*)p0 = make_float2(O[jd][0] * inv0, O[jd][1] * inv0);
        *(float2*)p1 = make_float2(O[jd][2] * inv1, O[jd][3] * inv1);
    }
}

// ---------------------------------------------------------------------------
extern "C" void kernel_launch(void* const* d_in, const int* in_sizes, int n_in,
                              void* d_out, int out_size)
{
    const float* x  = (const float*)d_in[0];
    const float* Wq = (const float*)d_in[1];
    const float* bq = (const float*)d_in[2];
    const float* Wv = (const float*)d_in[3];
    const float* bv = (const float*)d_in[4];
    const float* hp = (const float*)d_in[5];
    float* out = (float*)d_out;

    split_kernel<<<6144, 256>>>(x, Wq, Wv);
    whp_kernel<<<dim3(4, 96), 256>>>(Wq, bq, hp);

    const size_t bsmem = (size_t)(BK_B * 68 + BK_B * 96) * sizeof(float);
    cudaFuncSetAttribute(bucket_kernel,
                         cudaFuncAttributeMaxDynamicSharedMemorySize, (int)bsmem);
    bucket_kernel<<<64, 256, bsmem>>>(x);

    cudaFuncSetAttribute(proj_tc_kernel,
                         cudaFuncAttributeMaxDynamicSharedMemorySize,
                         2 * PJ_STAGE_B);
    proj_tc_kernel<<<dim3(8, 32, 2), 256, 2 * PJ_STAGE_B>>>(bq, bv);

    cudaFuncSetAttribute(attn_kernel,
                         cudaFuncAttributeMaxDynamicSharedMemorySize, AT_SMEM);
    attn_kernel<<<dim3(S_ / 64, B_ * H_), 128, AT_SMEM>>>(out);
}

// round 7
// speedup vs baseline: 4.4381x; 1.0002x over previous
#include <cuda_runtime.h>
#include <cuda_bf16.h>
#include <math.h>
#include <stdint.h>

#define B_ 2
#define S_ 2048
#define E_ 1024
#define H_ 16
#define DH 64

// Scratch (device globals — no allocation allowed)
__device__ __nv_bfloat16 g_xh[(size_t)B_ * S_ * E_];
__device__ __nv_bfloat16 g_xl[(size_t)B_ * S_ * E_];
__device__ __nv_bfloat16 g_Wqh[(size_t)E_ * E_];
__device__ __nv_bfloat16 g_Wql[(size_t)E_ * E_];
__device__ __nv_bfloat16 g_Wvh[(size_t)E_ * E_];
__device__ __nv_bfloat16 g_Wvl[(size_t)E_ * E_];
__device__ __nv_bfloat16 g_Qh[(size_t)B_ * H_ * S_ * DH];
__device__ __nv_bfloat16 g_Ql[(size_t)B_ * H_ * S_ * DH];
__device__ __nv_bfloat16 g_Vh[(size_t)B_ * H_ * S_ * DH];
__device__ __nv_bfloat16 g_Vl[(size_t)B_ * H_ * S_ * DH];
__device__ float g_Whp[(size_t)E_ * 96];     // [e][h*6+n]
__device__ float g_cbias[96];
__device__ int   g_bkt[B_ * H_ * S_];

typedef unsigned long long u64;
union F2 { u64 u; float2 f; };

__device__ __forceinline__ u64 dup2(float x) {
    u64 r; asm("mov.b64 %0,{%1,%1};" : "=l"(r) : "f"(x)); return r;
}
__device__ __forceinline__ void fma2(u64& d, u64 a, u64 b) {
    asm("fma.rn.f32x2 %0,%1,%2,%3;" : "=l"(d) : "l"(a), "l"(b), "l"(d));
}
__device__ __forceinline__ void ldsm4(uint32_t* r, uint32_t a) {
    asm volatile("ldmatrix.sync.aligned.m8n8.x4.shared.b16 {%0,%1,%2,%3},[%4];"
                 : "=r"(r[0]), "=r"(r[1]), "=r"(r[2]), "=r"(r[3]) : "r"(a));
}
__device__ __forceinline__ void ldsm4t(uint32_t* r, uint32_t a) {
    asm volatile("ldmatrix.sync.aligned.m8n8.x4.trans.shared.b16 {%0,%1,%2,%3},[%4];"
                 : "=r"(r[0]), "=r"(r[1]), "=r"(r[2]), "=r"(r[3]) : "r"(a));
}
__device__ __forceinline__ void mma16816(float* c, const uint32_t* a,
                                         uint32_t b0, uint32_t b1) {
    asm volatile(
        "mma.sync.aligned.m16n8k16.row.col.f32.bf16.bf16.f32 "
        "{%0,%1,%2,%3},{%4,%5,%6,%7},{%8,%9},{%0,%1,%2,%3};"
        : "+f"(c[0]), "+f"(c[1]), "+f"(c[2]), "+f"(c[3])
        : "r"(a[0]), "r"(a[1]), "r"(a[2]), "r"(a[3]), "r"(b0), "r"(b1));
}
__device__ __forceinline__ uint32_t packbf(float lo, float hi) {
    uint32_t r; asm("cvt.rn.bf16x2.f32 %0,%1,%2;" : "=r"(r) : "f"(hi), "f"(lo));
    return r;
}
__device__ __forceinline__ void cpa16(uint32_t dst, const void* src) {
    asm volatile("cp.async.cg.shared.global [%0],[%1],16;" :: "r"(dst), "l"(src));
}
__device__ __forceinline__ void cpa4(uint32_t dst, const void* src) {
    asm volatile("cp.async.ca.shared.global [%0],[%1],4;" :: "r"(dst), "l"(src));
}
#define CP_COMMIT() asm volatile("cp.async.commit_group;")
template <int N>
__device__ __forceinline__ void cp_wait() {
    asm volatile("cp.async.wait_group %0;" :: "n"(N));
}

// ---------------------------------------------------------------------------
// Split x, Wq, Wv into bf16 hi/lo pairs. 4 floats per thread.
// ---------------------------------------------------------------------------
__global__ __launch_bounds__(256)
void split_kernel(const float* __restrict__ x, const float* __restrict__ Wq,
                  const float* __restrict__ Wv)
{
    size_t idx4 = (size_t)blockIdx.x * 256 + threadIdx.x;
    size_t flat = idx4 * 4;
    const float* src; __nv_bfloat16* dh; __nv_bfloat16* dl; size_t off;
    const size_t NX = (size_t)B_ * S_ * E_;
    const size_t NW = (size_t)E_ * E_;
    if (flat < NX)            { src = x;  dh = g_xh;  dl = g_xl;  off = flat; }
    else if (flat < NX + NW)  { src = Wq; dh = g_Wqh; dl = g_Wql; off = flat - NX; }
    else                      { src = Wv; dh = g_Wvh; dl = g_Wvl; off = flat - NX - NW; }

    float4 v = *(const float4*)(src + off);
    float vv[4] = {v.x, v.y, v.z, v.w};
    __align__(8) __nv_bfloat16 hi[4], lo[4];
#pragma unroll
    for (int j = 0; j < 4; j++) {
        hi[j] = __float2bfloat16(vv[j]);
        lo[j] = __float2bfloat16(vv[j] - __bfloat162float(hi[j]));
    }
    *(uint2*)(dh + off) = *(const uint2*)hi;
    *(uint2*)(dl + off) = *(const uint2*)lo;
}

// ---------------------------------------------------------------------------
// Whp[e][h*6+n] = sum_d Wq[h*64+d][e] * hp[d][n]  ;  cbias[hn] too.
// ---------------------------------------------------------------------------
__global__ __launch_bounds__(256)
void whp_kernel(const float* __restrict__ Wq, const float* __restrict__ bq,
                const float* __restrict__ hp)
{
    const int hn = blockIdx.y;
    const int h = hn / 6, n = hn % 6;
    const int e = blockIdx.x * 256 + threadIdx.x;
    float acc = 0.f;
#pragma unroll 8
    for (int d = 0; d < 64; d++)
        acc = fmaf(Wq[(size_t)(h * 64 + d) * E_ + e], __ldg(hp + d * 6 + n), acc);
    g_Whp[(size_t)e * 96 + hn] = acc;
    if (blockIdx.x == 0 && threadIdx.x == 0) {
        float cb = hp[64 * 6 + n];
        for (int d = 0; d < 64; d++)
            cb = fmaf(bq[h * 64 + d], hp[d * 6 + n], cb);
        g_cbias[hn] = cb;
    }
}

// ---------------------------------------------------------------------------
// Bucket GEMM (fp32 f32x2): proj[m][hn] = x @ Whp + cbias; sign bits.
// ---------------------------------------------------------------------------
#define BK_B 128
__global__ __launch_bounds__(256)
void bucket_kernel(const float* __restrict__ x)
{
    extern __shared__ float bsm[];
    float* sx = bsm;                 // [BK_B][68]
    float* sw = bsm + BK_B * 68;     // [BK_B][96]

    const int tid = threadIdx.x;
    const int tx = tid & 31;
    const int ty = tid >> 5;
    const int m0 = blockIdx.x * 64;

    u64 acc[4][3];
#pragma unroll
    for (int p = 0; p < 4; p++)
#pragma unroll
        for (int c = 0; c < 3; c++) acc[p][c] = dup2(g_cbias[tx + 32 * c]);

    for (int k0 = 0; k0 < E_; k0 += BK_B) {
#pragma unroll
        for (int it = 0; it < 8; it++) {
            int idx = it * 256 + tid;
            int r = idx >> 5;
            int c4 = (idx & 31) << 2;
            float4 v = *(const float4*)(x + (size_t)(m0 + r) * E_ + k0 + c4);
            sx[(c4 + 0) * 68 + r] = v.x; sx[(c4 + 1) * 68 + r] = v.y;
            sx[(c4 + 2) * 68 + r] = v.z; sx[(c4 + 3) * 68 + r] = v.w;
        }
#pragma unroll
        for (int it = 0; it < 12; it++) {
            int u4 = it * 256 + tid;
            *(uint4*)(sw + u4 * 4) =
                *(const uint4*)(g_Whp + (size_t)k0 * 96 + u4 * 4);
        }
        __syncthreads();

#pragma unroll 4
        for (int k = 0; k < BK_B; k++) {
            ulonglong2 x01 = *(const ulonglong2*)(sx + k * 68 + 8 * ty);
            ulonglong2 x23 = *(const ulonglong2*)(sx + k * 68 + 8 * ty + 4);
            u64 xp[4] = {x01.x, x01.y, x23.x, x23.y};
            u64 w0 = dup2(sw[k * 96 + tx]);
            u64 w1 = dup2(sw[k * 96 + tx + 32]);
            u64 w2 = dup2(sw[k * 96 + tx + 64]);
#pragma unroll
            for (int p = 0; p < 4; p++) {
                fma2(acc[p][0], xp[p], w0);
                fma2(acc[p][1], xp[p], w1);
                fma2(acc[p][2], xp[p], w2);
            }
        }
        __syncthreads();
    }

    float* sproj = sx;
#pragma unroll
    for (int p = 0; p < 4; p++) {
#pragma unroll
        for (int c = 0; c < 3; c++) {
            F2 u; u.u = acc[p][c];
            sproj[(8 * ty + 2 * p) * 96 + tx + 32 * c]     = u.f.x;
            sproj[(8 * ty + 2 * p + 1) * 96 + tx + 32 * c] = u.f.y;
        }
    }
    __syncthreads();

#pragma unroll
    for (int u = 0; u < 4; u++) {
        int o = u * 256 + tid;
        int row = o >> 4, h = o & 15;
        int bucket = 0;
#pragma unroll
        for (int n = 0; n < 6; n++)
            if (sproj[row * 96 + h * 6 + n] >= 0.f) bucket |= (1 << n);
        int m = m0 + row;
        int b = m >> 11, s = m & (S_ - 1);
        g_bkt[(b * H_ + h) * S_ + s] = bucket;
    }
}

// ---------------------------------------------------------------------------
// Tensor-core projection GEMM (bf16 x3) with 2-stage cp.async pipeline.
// CTA 128x128, BK=32, 8 warps (4m x 2n). grid (8, 32, 2).
// Dynamic smem per stage: Ah|Al|Bh|Bl each 128*PST bf16.
// ---------------------------------------------------------------------------
#define PST 40
#define PJ_TILE_B (128 * PST * 2)          // 10240 B per array
#define PJ_STAGE_B (4 * PJ_TILE_B)         // 40960 B per stage

__global__ __launch_bounds__(256, 2)
void proj_tc_kernel(const float* __restrict__ bq, const float* __restrict__ bv)
{
    extern __shared__ char psm[];
    const uint32_t aS = (uint32_t)__cvta_generic_to_shared(psm);

    const int z = blockIdx.z;
    const __nv_bfloat16* Bh_g = z ? g_Wvh : g_Wqh;
    const __nv_bfloat16* Bl_g = z ? g_Wvl : g_Wql;
    const float* bias = z ? bv : bq;
    __nv_bfloat16* Hh = z ? g_Vh : g_Qh;
    __nv_bfloat16* Hl = z ? g_Vl : g_Ql;

    const int tid = threadIdx.x;
    const int wid = tid >> 5, lane = tid & 31;
    const int qid = lane >> 2, l2 = lane & 3;
    const int sel = lane >> 3, l7 = lane & 7;
    const int wm = wid & 3, wn = wid >> 2;
    const int m0 = blockIdx.y << 7;
    const int n0 = blockIdx.x << 7;

    // per-thread load coords (2 uint4-rows per thread per array)
    const int r_ld[2]  = { (tid * 2) >> 2, (tid * 2 + 1) >> 2 };
    const int cu_ld[2] = { ((tid * 2) & 3) << 3, ((tid * 2 + 1) & 3) << 3 };

    float C[2][8][4];
#pragma unroll
    for (int a = 0; a < 2; a++)
#pragma unroll
        for (int j = 0; j < 8; j++)
#pragma unroll
            for (int t = 0; t < 4; t++) C[a][j][t] = 0.f;

    const uint32_t aoff = (uint32_t)((wm * 32 + (sel & 1) * 8 + l7) * (PST * 2)
                                     + (sel >> 1) * 16);
    const uint32_t bhl = (sel < 2) ? (2 * PJ_TILE_B) : (3 * PJ_TILE_B);
    const uint32_t boff = bhl + (wn * 64 + l7) * (PST * 2) + (sel & 1) * 16;

    // prefetch helper (macro-ish lambda)
    auto prefetch = [&](int st, int k0) {
#pragma unroll
        for (int p = 0; p < 2; p++) {
            int r = r_ld[p], cu = cu_ld[p];
            size_t gx = (size_t)(m0 + r) * E_ + k0 + cu;
            size_t gw = (size_t)(n0 + r) * E_ + k0 + cu;
            uint32_t so = aS + st * PJ_STAGE_B + (r * PST + cu) * 2;
            cpa16(so,                 g_xh + gx);
            cpa16(so + PJ_TILE_B,     g_xl + gx);
            cpa16(so + 2 * PJ_TILE_B, Bh_g + gw);
            cpa16(so + 3 * PJ_TILE_B, Bl_g + gw);
        }
    };

    prefetch(0, 0);
    CP_COMMIT();

    for (int kt = 0; kt < 32; kt++) {
        if (kt + 1 < 32) prefetch((kt + 1) & 1, (kt + 1) * 32);
        CP_COMMIT();
        cp_wait<1>();
        __syncthreads();

        const uint32_t stB = aS + (kt & 1) * PJ_STAGE_B;
#pragma unroll
        for (int kk = 0; kk < 2; kk++) {
            uint32_t Ahf[2][4], Alf[2][4];
#pragma unroll
            for (int a = 0; a < 2; a++) {
                uint32_t ra = stB + aoff + a * 16 * (PST * 2) + kk * 32;
                ldsm4(Ahf[a], ra);
                ldsm4(Alf[a], ra + PJ_TILE_B);
            }
#pragma unroll
            for (int j = 0; j < 8; j++) {
                uint32_t bb[4];
                ldsm4(bb, stB + boff + j * 8 * (PST * 2) + kk * 32);
#pragma unroll
                for (int a = 0; a < 2; a++) {
                    mma16816(C[a][j], Ahf[a], bb[0], bb[1]);
                    mma16816(C[a][j], Alf[a], bb[0], bb[1]);
                    mma16816(C[a][j], Ahf[a], bb[2], bb[3]);
                }
            }
        }
        __syncthreads();
    }

    // epilogue: + bias (fp32), split hi/lo, scatter to [B,H,S,Dh]
#pragma unroll
    for (int a = 0; a < 2; a++) {
        int mrow = m0 + wm * 32 + a * 16 + qid;
#pragma unroll
        for (int j = 0; j < 8; j++) {
            int n = n0 + wn * 64 + j * 8 + 2 * l2;
            int h = n >> 6, d = n & 63;
            float b0 = bias[n], b1 = bias[n + 1];
#pragma unroll
            for (int half = 0; half < 2; half++) {
                int m = mrow + half * 8;
                int b = m >> 11, s = m & (S_ - 1);
                size_t off = (((size_t)(b * H_ + h)) * S_ + s) * DH + d;
                float v0 = C[a][j][2 * half + 0] + b0;
                float v1 = C[a][j][2 * half + 1] + b1;
                uint32_t hi = packbf(v0, v1);
                float l0 = v0 - __uint_as_float(hi << 16);
                float l1 = v1 - __uint_as_float(hi & 0xFFFF0000u);
                *(uint32_t*)(Hh + off) = hi;
                *(uint32_t*)(Hl + off) = packbf(l0, l1);
            }
        }
    }
}

// ---------------------------------------------------------------------------
// Tensor-core flash attention, 2-stage cp.async pipeline for K/V tiles.
// CTA: 128 threads (4 warps), s-tile 64, t-tiles 64.
// Dynamic smem: 2 stages x [Kh|Kl|Vh|Vl] (64 x RS bf16 each) + bk[2][64].
// ---------------------------------------------------------------------------
#define RS 72
#define RSB 144
#define AT_TILE_B (64 * RS * 2)            // 9216 B
#define AT_STAGE_B (4 * AT_TILE_B)         // 36864 B
#define AT_BK_OFF (2 * AT_STAGE_B)         // 73728 B
#define AT_SMEM (AT_BK_OFF + 2 * 64 * 4)   // 74240 B

__global__ __launch_bounds__(128)
void attn_kernel(float* __restrict__ out)
{
    extern __shared__ char asm_[];
    const uint32_t aS = (uint32_t)__cvta_generic_to_shared(asm_);
    __nv_bfloat16* sK0h = (__nv_bfloat16*)asm_;                  // stage0 Kh (Q staging)
    int* bkArr = (int*)(asm_ + AT_BK_OFF);

    const int tid = threadIdx.x;
    const int wid = tid >> 5, lane = tid & 31;
    const int qid = lane >> 2;
    const int l2  = lane & 3;
    const int sel = lane >> 3, l7 = lane & 7;

    const int bh = blockIdx.y;
    const int b = bh >> 4, h = bh & 15;
    const int s0 = blockIdx.x << 6;
    const __nv_bfloat16* Qh_g = g_Qh + (size_t)bh * S_ * DH;
    const __nv_bfloat16* Ql_g = g_Ql + (size_t)bh * S_ * DH;
    const __nv_bfloat16* Vh_g = g_Vh + (size_t)bh * S_ * DH;
    const __nv_bfloat16* Vl_g = g_Vl + (size_t)bh * S_ * DH;
    const int* bkp = g_bkt + bh * S_;

    // ---- stage Q tile into stage-0 Kh/Kl region, extract A fragments ----
#pragma unroll
    for (int i = tid; i < 512; i += 128) {
        int r = i >> 3, c = (i & 7) << 3;
        *(uint4*)(sK0h + r * RS + c) =
            *(const uint4*)(Qh_g + (size_t)(s0 + r) * DH + c);
        *(uint4*)((__nv_bfloat16*)(asm_ + AT_TILE_B) + r * RS + c) =
            *(const uint4*)(Ql_g + (size_t)(s0 + r) * DH + c);
    }
    __syncthreads();

    uint32_t Ah[4][4], Al[4][4];
    {
        uint32_t qoff = aS + (uint32_t)((wid * 16 + (sel & 1) * 8 + l7) * RSB
                                        + (sel >> 1) * 16);
#pragma unroll
        for (int u = 0; u < 4; u++) {
            ldsm4(Ah[u], qoff + u * 32);
            ldsm4(Al[u], qoff + u * 32 + AT_TILE_B);
        }
    }
    const int bq0 = bkp[s0 + wid * 16 + qid];
    const int bq1 = bkp[s0 + wid * 16 + qid + 8];
    __syncthreads();   // done reading Q staging before prefetch overwrites

    float O[8][4];
#pragma unroll
    for (int j = 0; j < 8; j++)
#pragma unroll
        for (int k = 0; k < 4; k++) O[j][k] = 0.f;
    float m0 = -INFINITY, m1 = -INFINITY, l0 = 0.f, l1 = 0.f;

    const uint32_t khl = (sel < 2) ? 0u : (uint32_t)AT_TILE_B;
    const uint32_t kb_off = khl + l7 * RSB + (sel & 1) * 16;
    const uint32_t vhl = (sel < 2) ? (uint32_t)(2 * AT_TILE_B)
                                   : (uint32_t)(3 * AT_TILE_B);
    const uint32_t vb_off = vhl + (l7 + (sel & 1) * 8) * RSB;

    auto prefetch = [&](int st, int t0) {
#pragma unroll
        for (int i = tid; i < 512; i += 128) {
            int r = i >> 3, c = (i & 7) << 3;
            size_t go = (size_t)(t0 + r) * DH + c;
            uint32_t so = aS + st * AT_STAGE_B + (r * RS + c) * 2;
            cpa16(so,                 Qh_g + go);
            cpa16(so + AT_TILE_B,     Ql_g + go);
            cpa16(so + 2 * AT_TILE_B, Vh_g + go);
            cpa16(so + 3 * AT_TILE_B, Vl_g + go);
        }
        if (tid < 64)
            cpa4(aS + AT_BK_OFF + (st * 64 + tid) * 4, bkp + t0 + tid);
    };

    prefetch(0, 0);
    CP_COMMIT();

    for (int it = 0; it < S_ / 64; it++) {
        if (it + 1 < S_ / 64) prefetch((it + 1) & 1, (it + 1) * 64);
        CP_COMMIT();
        cp_wait<1>();
        __syncthreads();

        const int st = it & 1;
        const uint32_t stB = aS + st * AT_STAGE_B;
        const int* bks = bkArr + st * 64;

        // ---- S = Q K^T (x3 split) ----
        float C[8][4];
#pragma unroll
        for (int j = 0; j < 8; j++)
#pragma unroll
            for (int k = 0; k < 4; k++) C[j][k] = 0.f;

#pragma unroll
        for (int j = 0; j < 8; j++) {
#pragma unroll
            for (int u = 0; u < 4; u++) {
                uint32_t kb[4];
                ldsm4(kb, stB + kb_off + j * (8 * RSB) + u * 32);
                mma16816(C[j], Ah[u], kb[0], kb[1]);
                mma16816(C[j], Al[u], kb[0], kb[1]);
                mma16816(C[j], Ah[u], kb[2], kb[3]);
            }
        }

        // ---- coeff + online softmax ----
        float rmax0 = -INFINITY, rmax1 = -INFINITY;
#pragma unroll
        for (int j = 0; j < 8; j++) {
            int tcol = 8 * j + 2 * l2;
            int bk0 = bks[tcol], bk1 = bks[tcol + 1];
            float cf00 = (bq0 == bk0) ? 1.96875f : 1.9375f;
            float cf01 = (bq0 == bk1) ? 1.96875f : 1.9375f;
            float cf10 = (bq1 == bk0) ? 1.96875f : 1.9375f;
            float cf11 = (bq1 == bk1) ? 1.96875f : 1.9375f;
            C[j][0] *= cf00; C[j][1] *= cf01;
            C[j][2] *= cf10; C[j][3] *= cf11;
            rmax0 = fmaxf(rmax0, fmaxf(C[j][0], C[j][1]));
            rmax1 = fmaxf(rmax1, fmaxf(C[j][2], C[j][3]));
        }
        rmax0 = fmaxf(rmax0, __shfl_xor_sync(0xffffffffu, rmax0, 1));
        rmax0 = fmaxf(rmax0, __shfl_xor_sync(0xffffffffu, rmax0, 2));
        rmax1 = fmaxf(rmax1, __shfl_xor_sync(0xffffffffu, rmax1, 1));
        rmax1 = fmaxf(rmax1, __shfl_xor_sync(0xffffffffu, rmax1, 2));

        float mn0 = fmaxf(m0, rmax0);
        float mn1 = fmaxf(m1, rmax1);
        float corr0 = __expf(m0 - mn0);
        float corr1 = __expf(m1 - mn1);
        m0 = mn0; m1 = mn1;

        float sum0 = 0.f, sum1 = 0.f;
#pragma unroll
        for (int j = 0; j < 8; j++) {
            C[j][0] = __expf(C[j][0] - mn0);
            C[j][1] = __expf(C[j][1] - mn0);
            C[j][2] = __expf(C[j][2] - mn1);
            C[j][3] = __expf(C[j][3] - mn1);
            sum0 += C[j][0] + C[j][1];
            sum1 += C[j][2] + C[j][3];
        }
        sum0 += __shfl_xor_sync(0xffffffffu, sum0, 1);
        sum0 += __shfl_xor_sync(0xffffffffu, sum0, 2);
        sum1 += __shfl_xor_sync(0xffffffffu, sum1, 1);
        sum1 += __shfl_xor_sync(0xffffffffu, sum1, 2);
        l0 = l0 * corr0 + sum0;
        l1 = l1 * corr1 + sum1;

#pragma unroll
        for (int j = 0; j < 8; j++) {
            O[j][0] *= corr0; O[j][1] *= corr0;
            O[j][2] *= corr1; O[j][3] *= corr1;
        }

        // ---- O += P V (x3 split) ----
#pragma unroll
        for (int u = 0; u < 4; u++) {
            uint32_t ph[4], pl[4];
#pragma unroll
            for (int half = 0; half < 2; half++) {
                const float* cc = C[2 * u + half];
                uint32_t h0 = packbf(cc[0], cc[1]);
                uint32_t h1 = packbf(cc[2], cc[3]);
                float r00 = cc[0] - __uint_as_float(h0 << 16);
                float r01 = cc[1] - __uint_as_float(h0 & 0xFFFF0000u);
                float r10 = cc[2] - __uint_as_float(h1 << 16);
                float r11 = cc[3] - __uint_as_float(h1 & 0xFFFF0000u);
                ph[2 * half]     = h0;
                ph[2 * half + 1] = h1;
                pl[2 * half]     = packbf(r00, r01);
                pl[2 * half + 1] = packbf(r10, r11);
            }
#pragma unroll
            for (int jd = 0; jd < 8; jd++) {
                uint32_t vb[4];
                ldsm4t(vb, stB + vb_off + u * (16 * RSB) + jd * 16);
                mma16816(O[jd], ph, vb[0], vb[1]);
                mma16816(O[jd], pl, vb[0], vb[1]);
                mma16816(O[jd], ph, vb[2], vb[3]);
            }
        }
        __syncthreads();   // all warps done with this stage before overwrite
    }

    const float inv0 = 1.f / l0;
    const float inv1 = 1.f / l1;
    const int srow0 = s0 + wid * 16 + qid;
    const int srow1 = srow0 + 8;
#pragma unroll
    for (int jd = 0; jd < 8; jd++) {
        int d = 8 * jd + 2 * l2;
        float* p0 = out + (((size_t)(b * S_ + srow0)) * H_ + h) * DH + d;
        float* p1 = out + (((size_t)(b * S_ + srow1)) * H_ + h) * DH + d;
        *(float2*)p0 = make_float2(O[jd][0] * inv0, O[jd][1] * inv0);
        *(float2*)p1 = make_float2(O[jd][2] * inv1, O[jd][3] * inv1);
    }
}

// ---------------------------------------------------------------------------
extern "C" void kernel_launch(void* const* d_in, const int* in_sizes, int n_in,
                              void* d_out, int out_size)
{
    const float* x  = (const float*)d_in[0];
    const float* Wq = (const float*)d_in[1];
    const float* bq = (const float*)d_in[2];
    const float* Wv = (const float*)d_in[3];
    const float* bv = (const float*)d_in[4];
    const float* hp = (const float*)d_in[5];
    float* out = (float*)d_out;

    split_kernel<<<6144, 256>>>(x, Wq, Wv);
    whp_kernel<<<dim3(4, 96), 256>>>(Wq, bq, hp);

    const size_t bsmem = (size_t)(BK_B * 68 + BK_B * 96) * sizeof(float);
    cudaFuncSetAttribute(bucket_kernel,
                         cudaFuncAttributeMaxDynamicSharedMemorySize, (int)bsmem);
    bucket_kernel<<<64, 256, bsmem>>>(x);

    cudaFuncSetAttribute(proj_tc_kernel,
                         cudaFuncAttributeMaxDynamicSharedMemorySize,
                         2 * PJ_STAGE_B);
    proj_tc_kernel<<<dim3(8, 32, 2), 256, 2 * PJ_STAGE_B>>>(bq, bv);

    cudaFuncSetAttribute(attn_kernel,
                         cudaFuncAttributeMaxDynamicSharedMemorySize, AT_SMEM);
    attn_kernel<<<dim3(S_ / 64, B_ * H_), 128, AT_SMEM>>>(out);
}